// round 5
// baseline (speedup 1.0000x reference)
#include <cuda_runtime.h>
#include <math.h>
#include <stdint.h>

#define DDIM 256
#define CDIM 10
#define MAXN 500000
#define MAXG 100000
#define K1DIM 272

__device__ float g_Y1[(long long)MAXN * DDIM];    // tf32-rounded gelu(x@W1a+b1a)
__device__ float g_sums[(long long)MAXG * DDIM];
__device__ float g_cnt[MAXG];
__device__ float g_inv[MAXG];
__device__ float g_T[(long long)MAXG * DDIM];
__device__ float g_Wt1[DDIM * K1DIM];             // Wt[n][k] tf32-rounded
__device__ float g_Wt2[DDIM * DDIM];
__device__ float g_Wt3[DDIM * DDIM];

__device__ __forceinline__ float gelu_f(float x) {
    return 0.5f * x * (1.0f + erff(x * 0.70710678118654752f));
}
__device__ __forceinline__ float to_tf32(float x) {
    float r;
    asm("cvt.rna.tf32.f32 %0, %1;" : "=f"(r) : "f"(x));
    return r;
}
__device__ __forceinline__ void mma_tf32(float c[4], const unsigned a[4],
                                         unsigned b0, unsigned b1) {
    asm volatile(
        "mma.sync.aligned.m16n8k8.row.col.f32.tf32.tf32.f32 "
        "{%0,%1,%2,%3},{%4,%5,%6,%7},{%8,%9},{%0,%1,%2,%3};"
        : "+f"(c[0]), "+f"(c[1]), "+f"(c[2]), "+f"(c[3])
        : "r"(a[0]), "r"(a[1]), "r"(a[2]), "r"(a[3]), "r"(b0), "r"(b1));
}
__device__ __forceinline__ void ldsm4(unsigned &d0, unsigned &d1, unsigned &d2,
                                      unsigned &d3, unsigned addr) {
    asm volatile("ldmatrix.sync.aligned.m8n8.x4.shared.b16 {%0,%1,%2,%3}, [%4];"
                 : "=r"(d0), "=r"(d1), "=r"(d2), "=r"(d3) : "r"(addr));
}
__device__ __forceinline__ void cp16_pred(uint32_t dst, const void* src, bool pred) {
    const int sz = pred ? 16 : 0;
    asm volatile("cp.async.cg.shared.global [%0], [%1], 16, %2;"
                 :: "r"(dst), "l"(src), "r"(sz) : "memory");
}
__device__ __forceinline__ void cp16_ca(uint32_t dst, const void* src) {
    asm volatile("cp.async.ca.shared.global [%0], [%1], 16;"
                 :: "r"(dst), "l"(src) : "memory");
}
#define CP_COMMIT() asm volatile("cp.async.commit_group;" ::: "memory")
#define CP_WAIT2()  asm volatile("cp.async.wait_group 2;" ::: "memory")

// ===========================================================================
// GEMM1 (R3 register-staged path, MODE0 only): C = concat(h,sf) @ Wt1^T
// block 128x128, 8 warps (4x2), BK=16, tf32 mma + ldmatrix, double buffer.
// Epilogue stores tf32-rounded gelu -> g_Y1.
// ===========================================================================
__global__ __launch_bounds__(256, 2) void gemm1_tc(
    const float* __restrict__ Ah, const float* __restrict__ Asf,
    const float* __restrict__ Wt, const float* __restrict__ bias,
    int Mrows, int Kdim)
{
    __shared__ float4 As4[2][512];
    __shared__ float4 Bs4[2][512];

    const int tid  = threadIdx.x;
    const int lane = tid & 31;
    const int warp = tid >> 5;
    const int wm   = warp >> 1;
    const int wn   = warp & 1;
    const int row0 = blockIdx.y * 128;
    const int col0 = blockIdx.x * 128;

    const unsigned Abase = (unsigned)__cvta_generic_to_shared(&As4[0][0]);
    const unsigned Bbase = (unsigned)__cvta_generic_to_shared(&Bs4[0][0]);

    float acc[2][8][4];
#pragma unroll
    for (int i = 0; i < 2; i++)
#pragma unroll
        for (int j = 0; j < 8; j++)
#pragma unroll
            for (int k = 0; k < 4; k++) acc[i][j][k] = 0.f;

    const int am   = tid >> 2;
    const int aslt = tid & 3;
    const int bn   = tid >> 1;
    const int bs0  = (tid & 1) * 2;

    const int q  = lane >> 3;
    const int l8 = lane & 7;
    const int a_moff = l8 + 8 * (q & 1);
    const int a_sadd = q >> 1;
    const int b_noff = l8 + 8 * (q >> 1);
    const int b_sadd = q & 1;

    const int nChunks = Kdim >> 4;

    float4 av[2], bv[2];
    {
#pragma unroll
        for (int h2 = 0; h2 < 2; h2++) {
            const int m = am + 64 * h2;
            const int arow = row0 + m;
            float4 v = make_float4(0.f, 0.f, 0.f, 0.f);
            if (arow < Mrows) {
                const int k = aslt * 4;
                v = (k < DDIM) ? *(const float4*)(Ah + (long long)arow * DDIM + k)
                               : *(const float4*)(Asf + (long long)arow * 16 + (k - DDIM));
            }
            av[h2] = v;
        }
#pragma unroll
        for (int s = 0; s < 2; s++)
            bv[s] = *(const float4*)(Wt + (long long)(col0 + bn) * Kdim + (bs0 + s) * 4);
    }

    int buf = 0;
    for (int t = 0; t < nChunks; ++t) {
#pragma unroll
        for (int h2 = 0; h2 < 2; h2++) {
            const int m = am + 64 * h2;
            float4 v = av[h2];
            v.x = to_tf32(v.x); v.y = to_tf32(v.y);
            v.z = to_tf32(v.z); v.w = to_tf32(v.w);
            As4[buf][(m * 64 + 16 * (aslt ^ ((m >> 1) & 3))) >> 4] = v;
        }
#pragma unroll
        for (int s = 0; s < 2; s++) {
            const int slot = bs0 + s;
            Bs4[buf][(bn * 64 + 16 * (slot ^ ((bn >> 1) & 3))) >> 4] = bv[s];
        }
        __syncthreads();

        if (t + 1 < nChunks) {
            const int k0 = (t + 1) << 4;
#pragma unroll
            for (int h2 = 0; h2 < 2; h2++) {
                const int m = am + 64 * h2;
                const int arow = row0 + m;
                float4 v = make_float4(0.f, 0.f, 0.f, 0.f);
                if (arow < Mrows) {
                    const int k = k0 + aslt * 4;
                    v = (k < DDIM) ? *(const float4*)(Ah + (long long)arow * DDIM + k)
                                   : *(const float4*)(Asf + (long long)arow * 16 + (k - DDIM));
                }
                av[h2] = v;
            }
#pragma unroll
            for (int s = 0; s < 2; s++)
                bv[s] = *(const float4*)(Wt + (long long)(col0 + bn) * Kdim + k0 + (bs0 + s) * 4);
        }

        const unsigned Ab = Abase + buf * 8192;
        const unsigned Bb = Bbase + buf * 8192;
#pragma unroll
        for (int ks = 0; ks < 2; ks++) {
            unsigned a[2][4];
#pragma unroll
            for (int mt = 0; mt < 2; mt++) {
                const int m = wm * 32 + mt * 16 + a_moff;
                const unsigned addr = Ab + m * 64 + 16 * ((2 * ks + a_sadd) ^ ((a_moff >> 1) & 3));
                ldsm4(a[mt][0], a[mt][1], a[mt][2], a[mt][3], addr);
            }
#pragma unroll
            for (int ntp = 0; ntp < 4; ntp++) {
                const int n = wn * 64 + ntp * 16 + b_noff;
                const unsigned addr = Bb + n * 64 + 16 * ((2 * ks + b_sadd) ^ ((b_noff >> 1) & 3));
                unsigned b0, b1, b2, b3;
                ldsm4(b0, b1, b2, b3, addr);
                mma_tf32(acc[0][2 * ntp], a[0], b0, b1);
                mma_tf32(acc[1][2 * ntp], a[1], b0, b1);
                mma_tf32(acc[0][2 * ntp + 1], a[0], b2, b3);
                mma_tf32(acc[1][2 * ntp + 1], a[1], b2, b3);
            }
        }
        if (t + 1 < nChunks) __syncthreads();
        buf ^= 1;
    }

    const int g   = lane >> 2;
    const int tig = lane & 3;
#pragma unroll
    for (int nt = 0; nt < 8; nt++) {
        const int c = col0 + wn * 64 + nt * 8 + tig * 2;
        const float bv0 = bias[c];
        const float bv1 = bias[c + 1];
#pragma unroll
        for (int mt = 0; mt < 2; mt++) {
            const int r1 = row0 + wm * 32 + mt * 16 + g;
            if (r1 < Mrows) {
                float2 o;
                o.x = to_tf32(gelu_f(acc[mt][nt][0] + bv0));
                o.y = to_tf32(gelu_f(acc[mt][nt][1] + bv1));
                *(float2*)(g_Y1 + (long long)r1 * DDIM + c) = o;
            }
            const int r2 = r1 + 8;
            if (r2 < Mrows) {
                float2 o;
                o.x = to_tf32(gelu_f(acc[mt][nt][2] + bv0));
                o.y = to_tf32(gelu_f(acc[mt][nt][3] + bv1));
                *(float2*)(g_Y1 + (long long)r2 * DDIM + c) = o;
            }
        }
    }
}

// ===========================================================================
// cp.async 4-stage pipelined GEMM (A and B pre-tf32-rounded in gmem).
// MODE 1: A = g_Y1;    epilogue (.+b) -> run-length segment-sum atomics
// MODE 2: A = g_sums;  epilogue gelu(inv[row]*acc + b) -> g_T
// Stage layout: stage s at s*16KB: A tile 8KB, B tile 8KB. K=256, BK=16.
// ===========================================================================
#define STAGES 4
#define STAGE_BYTES 16384
#define CP_SMEM (STAGES * STAGE_BYTES)

template <int MODE>
__global__ __launch_bounds__(256) void gemm_cp(
    const float* __restrict__ Wt, const float* __restrict__ bias,
    const int* __restrict__ seg, int Mrows)
{
    extern __shared__ char smem[];
    const uint32_t sbase = (uint32_t)__cvta_generic_to_shared(smem);
    float* ebuf = (float*)smem;                 // 16 x 130 floats (overlay)
    int* sseg = (int*)(smem + 16 * 130 * 4);    // 128 ints (overlay)

    const int tid  = threadIdx.x;
    const int lane = tid & 31;
    const int warp = tid >> 5;
    const int wm   = warp >> 1;
    const int wn   = warp & 1;
    const int row0 = blockIdx.y * 128;
    const int col0 = blockIdx.x * 128;

    const float* Asrc = (MODE == 1) ? g_Y1 : g_sums;

    float acc[2][8][4];
#pragma unroll
    for (int i = 0; i < 2; i++)
#pragma unroll
        for (int j = 0; j < 8; j++)
#pragma unroll
            for (int k = 0; k < 4; k++) acc[i][j][k] = 0.f;

    // loader mapping: row = tid>>1 (0..127), slots {2*(tid&1), +1}
    const int lrow = tid >> 1;
    const int ls0  = (tid & 1) * 2;
    const int arow = row0 + lrow;
    const bool apred = (arow < Mrows);
    const float* aptr = Asrc + (long long)arow * DDIM;
    const float* bptr = Wt + (long long)(col0 + lrow) * DDIM;
    const unsigned aoff0 = lrow * 64 + 16 * ((ls0 + 0) ^ ((lrow >> 1) & 3));
    const unsigned aoff1 = lrow * 64 + 16 * ((ls0 + 1) ^ ((lrow >> 1) & 3));

    const int q  = lane >> 3;
    const int l8 = lane & 7;
    const int a_moff = l8 + 8 * (q & 1);
    const int a_sadd = q >> 1;
    const int b_noff = l8 + 8 * (q >> 1);
    const int b_sadd = q & 1;

    const int nChunks = DDIM >> 4;   // 16

    // prologue: stages 0..STAGES-2
#pragma unroll
    for (int s = 0; s < STAGES - 1; s++) {
        const int k0 = s << 4;
        const uint32_t st = sbase + s * STAGE_BYTES;
        cp16_pred(st + aoff0, aptr + k0 + (ls0 + 0) * 4, apred);
        cp16_pred(st + aoff1, aptr + k0 + (ls0 + 1) * 4, apred);
        cp16_ca(st + 8192 + aoff0, bptr + k0 + (ls0 + 0) * 4);
        cp16_ca(st + 8192 + aoff1, bptr + k0 + (ls0 + 1) * 4);
        CP_COMMIT();
    }

    for (int t = 0; t < nChunks; ++t) {
        CP_WAIT2();
        __syncthreads();

        const int tf = t + STAGES - 1;
        if (tf < nChunks) {
            const int k0 = tf << 4;
            const uint32_t st = sbase + (tf & (STAGES - 1)) * STAGE_BYTES;
            cp16_pred(st + aoff0, aptr + k0 + (ls0 + 0) * 4, apred);
            cp16_pred(st + aoff1, aptr + k0 + (ls0 + 1) * 4, apred);
            cp16_ca(st + 8192 + aoff0, bptr + k0 + (ls0 + 0) * 4);
            cp16_ca(st + 8192 + aoff1, bptr + k0 + (ls0 + 1) * 4);
        }
        CP_COMMIT();   // commit every iteration keeps wait_group(2) exact

        const uint32_t stage = sbase + (t & (STAGES - 1)) * STAGE_BYTES;
        const uint32_t Ab = stage;
        const uint32_t Bb = stage + 8192;
#pragma unroll
        for (int ks = 0; ks < 2; ks++) {
            unsigned a[2][4];
#pragma unroll
            for (int mt = 0; mt < 2; mt++) {
                const int m = wm * 32 + mt * 16 + a_moff;
                const unsigned addr = Ab + m * 64 + 16 * ((2 * ks + a_sadd) ^ ((a_moff >> 1) & 3));
                ldsm4(a[mt][0], a[mt][1], a[mt][2], a[mt][3], addr);
            }
#pragma unroll
            for (int ntp = 0; ntp < 4; ntp++) {
                const int n = wn * 64 + ntp * 16 + b_noff;
                const unsigned addr = Bb + n * 64 + 16 * ((2 * ks + b_sadd) ^ ((b_noff >> 1) & 3));
                unsigned b0, b1, b2, b3;
                ldsm4(b0, b1, b2, b3, addr);
                mma_tf32(acc[0][2 * ntp], a[0], b0, b1);
                mma_tf32(acc[1][2 * ntp], a[1], b0, b1);
                mma_tf32(acc[0][2 * ntp + 1], a[0], b2, b3);
                mma_tf32(acc[1][2 * ntp + 1], a[1], b2, b3);
            }
        }
        __syncthreads();
    }

    // ---------------- epilogue ----------------
    const int g   = lane >> 2;
    const int tig = lane & 3;
    if (MODE == 2) {
#pragma unroll
        for (int nt = 0; nt < 8; nt++) {
            const int c = col0 + wn * 64 + nt * 8 + tig * 2;
            const float bv0 = bias[c];
            const float bv1 = bias[c + 1];
#pragma unroll
            for (int mt = 0; mt < 2; mt++) {
                const int r1 = row0 + wm * 32 + mt * 16 + g;
                if (r1 < Mrows) {
                    const float sc = g_inv[r1];
                    float2 o;
                    o.x = gelu_f(sc * acc[mt][nt][0] + bv0);
                    o.y = gelu_f(sc * acc[mt][nt][1] + bv1);
                    *(float2*)(g_T + (long long)r1 * DDIM + c) = o;
                }
                const int r2 = r1 + 8;
                if (r2 < Mrows) {
                    const float sc = g_inv[r2];
                    float2 o;
                    o.x = gelu_f(sc * acc[mt][nt][2] + bv0);
                    o.y = gelu_f(sc * acc[mt][nt][3] + bv1);
                    *(float2*)(g_T + (long long)r2 * DDIM + c) = o;
                }
            }
        }
    } else {
        for (int i = tid; i < 128; i += 256) {
            const int r = row0 + i;
            sseg[i] = (r < Mrows) ? seg[r] : -1;
        }
        __syncthreads();

        int cur = -1;
        float run = 0.f;
        const float bcol = (tid < 128) ? bias[col0 + tid] : 0.f;
#pragma unroll
        for (int p = 0; p < 8; p++) {
            const int pwm = p >> 1, pmt = p & 1;
            if (wm == pwm) {
#pragma unroll
                for (int nt = 0; nt < 8; nt++) {
                    const int cl = wn * 64 + nt * 8 + tig * 2;
                    ebuf[g * 130 + cl]           = acc[pmt][nt][0];
                    ebuf[g * 130 + cl + 1]       = acc[pmt][nt][1];
                    ebuf[(g + 8) * 130 + cl]     = acc[pmt][nt][2];
                    ebuf[(g + 8) * 130 + cl + 1] = acc[pmt][nt][3];
                }
            }
            __syncthreads();
            if (tid < 128) {
                for (int r = 0; r < 16; r++) {
                    const int grow = row0 + p * 16 + r;
                    if (grow < Mrows) {
                        const int s = sseg[p * 16 + r];
                        const float v = ebuf[r * 130 + tid] + bcol;
                        if (s != cur) {
                            if (cur >= 0)
                                atomicAdd(&g_sums[(long long)cur * DDIM + col0 + tid], run);
                            cur = s;
                            run = v;
                        } else {
                            run += v;
                        }
                    }
                }
            }
            __syncthreads();
        }
        if (tid < 128 && cur >= 0)
            atomicAdd(&g_sums[(long long)cur * DDIM + col0 + tid], run);
    }
}

// ---------------------------------------------------------------------------
__global__ void prep_w(const float* __restrict__ W, float* __restrict__ Wt, int K) {
    const int idx = blockIdx.x * blockDim.x + threadIdx.x;
    if (idx < K * DDIM) {
        const int k = idx / DDIM, n = idx % DDIM;
        Wt[n * K + k] = to_tf32(W[idx]);
    }
}

__global__ void zero_kernel(int G) {
    const long long total = (long long)G * DDIM;
    const long long stride = (long long)gridDim.x * blockDim.x;
    for (long long i = (long long)blockIdx.x * blockDim.x + threadIdx.x; i < total; i += stride)
        g_sums[i] = 0.f;
    for (long long i = (long long)blockIdx.x * blockDim.x + threadIdx.x; i < G; i += stride)
        g_cnt[i] = 0.f;
}

__global__ void count_kernel(const int* __restrict__ seg, int N) {
    const int i = blockIdx.x * blockDim.x + threadIdx.x;
    if (i < N) atomicAdd(&g_cnt[seg[i]], 1.0f);
}

__global__ void inv_kernel(int G) {
    const int i = blockIdx.x * blockDim.x + threadIdx.x;
    if (i < G) g_inv[i] = 1.0f / fmaxf(g_cnt[i], 1.0f);
}

__global__ __launch_bounds__(128) void head_kernel(
    const float* __restrict__ Wc2, const float* __restrict__ bc2,
    float* __restrict__ out, int G)
{
    __shared__ float sW[DDIM * CDIM];
    __shared__ float sb[CDIM];
    const int tid = threadIdx.x;
    for (int i = tid; i < DDIM * CDIM; i += 128) sW[i] = Wc2[i];
    if (tid < CDIM) sb[tid] = bc2[tid];
    __syncthreads();

    const int warp = tid >> 5;
    const int lane = tid & 31;
    const int g = blockIdx.x * 4 + warp;
    if (g >= G) return;

    const float* t = g_T + (long long)g * DDIM;
    const float4 v0 = *(const float4*)(t + lane * 8);
    const float4 v1 = *(const float4*)(t + lane * 8 + 4);
    const float tv[8] = {v0.x, v0.y, v0.z, v0.w, v1.x, v1.y, v1.z, v1.w};

    float acc[CDIM];
#pragma unroll
    for (int c = 0; c < CDIM; c++) acc[c] = 0.f;
#pragma unroll
    for (int u = 0; u < 8; u++) {
        const float* w = &sW[(lane * 8 + u) * CDIM];
#pragma unroll
        for (int c = 0; c < CDIM; c++) acc[c] += tv[u] * w[c];
    }
#pragma unroll
    for (int off = 16; off > 0; off >>= 1)
#pragma unroll
        for (int c = 0; c < CDIM; c++) acc[c] += __shfl_down_sync(0xffffffffu, acc[c], off);

    if (lane == 0) {
#pragma unroll
        for (int c = 0; c < CDIM; c++) out[(long long)g * CDIM + c] = acc[c] + sb[c];
    }
}

// ---------------------------------------------------------------------------
extern "C" void kernel_launch(void* const* d_in, const int* in_sizes, int n_in,
                              void* d_out, int out_size)
{
    const float* h   = (const float*)d_in[0];
    const float* sf  = (const float*)d_in[1];
    const float* W1a = (const float*)d_in[2];
    const float* b1a = (const float*)d_in[3];
    const float* W2a = (const float*)d_in[4];
    const float* b2a = (const float*)d_in[5];
    const float* Wc1 = (const float*)d_in[6];
    const float* bc1 = (const float*)d_in[7];
    const float* Wc2 = (const float*)d_in[8];
    const float* bc2 = (const float*)d_in[9];
    const int* seg   = (const int*)d_in[10];
    float* out = (float*)d_out;

    const int D = in_sizes[3];
    const int N = in_sizes[0] / D;
    const int C = in_sizes[8] / D;
    const int G = out_size / C;
    const int K1 = D + in_sizes[1] / N;   // 272

    float* wt1; cudaGetSymbolAddress((void**)&wt1, g_Wt1);
    float* wt2; cudaGetSymbolAddress((void**)&wt2, g_Wt2);
    float* wt3; cudaGetSymbolAddress((void**)&wt3, g_Wt3);

    cudaFuncSetAttribute(gemm_cp<1>, cudaFuncAttributeMaxDynamicSharedMemorySize, CP_SMEM);
    cudaFuncSetAttribute(gemm_cp<2>, cudaFuncAttributeMaxDynamicSharedMemorySize, CP_SMEM);

    prep_w<<<(K1 * D + 255) / 256, 256>>>(W1a, wt1, K1);
    prep_w<<<(D * D + 255) / 256, 256>>>(W2a, wt2, D);
    prep_w<<<(D * D + 255) / 256, 256>>>(Wc1, wt3, D);
    zero_kernel<<<2048, 256>>>(G);
    count_kernel<<<(N + 255) / 256, 256>>>(seg, N);
    gemm1_tc<<<dim3(2, (N + 127) / 128), 256>>>(h, sf, wt1, b1a, N, K1);
    gemm_cp<1><<<dim3(2, (N + 127) / 128), 256, CP_SMEM>>>(wt2, b2a, seg, N);
    inv_kernel<<<(G + 255) / 256, 256>>>(G);
    gemm_cp<2><<<dim3(2, (G + 127) / 128), 256, CP_SMEM>>>(wt3, bc1, nullptr, G);
    head_kernel<<<(G + 3) / 4, 128>>>(Wc2, bc2, out, G);
}

// round 6
// speedup vs baseline: 1.1657x; 1.1657x over previous
#include <cuda_runtime.h>
#include <math.h>
#include <stdint.h>

#define DDIM 256
#define CDIM 10
#define MAXN 500000
#define MAXG 100000

__device__ float g_sums[(long long)MAXG * DDIM];
__device__ float g_cnt[MAXG];
__device__ float g_inv[MAXG];
__device__ float g_T[(long long)MAXG * DDIM];
__device__ float g_Wt1[DDIM * 272];   // Wt[n][k] tf32-rounded
__device__ float g_Wt2[DDIM * DDIM];
__device__ float g_Wt3[DDIM * DDIM];

__device__ __forceinline__ float gelu_f(float x) {
    return 0.5f * x * (1.0f + erff(x * 0.70710678118654752f));
}
__device__ __forceinline__ float to_tf32(float x) {
    float r;
    asm("cvt.rna.tf32.f32 %0, %1;" : "=f"(r) : "f"(x));
    return r;
}
__device__ __forceinline__ void mma_tf32(float c[4], const unsigned a[4],
                                         unsigned b0, unsigned b1) {
    asm volatile(
        "mma.sync.aligned.m16n8k8.row.col.f32.tf32.tf32.f32 "
        "{%0,%1,%2,%3},{%4,%5,%6,%7},{%8,%9},{%0,%1,%2,%3};"
        : "+f"(c[0]), "+f"(c[1]), "+f"(c[2]), "+f"(c[3])
        : "r"(a[0]), "r"(a[1]), "r"(a[2]), "r"(a[3]), "r"(b0), "r"(b1));
}
__device__ __forceinline__ void ldsm4(unsigned &d0, unsigned &d1, unsigned &d2,
                                      unsigned &d3, unsigned addr) {
    asm volatile("ldmatrix.sync.aligned.m8n8.x4.shared.b16 {%0,%1,%2,%3}, [%4];"
                 : "=r"(d0), "=r"(d1), "=r"(d2), "=r"(d3) : "r"(addr));
}

// ---- fused kernel smem layout (bytes) ----
#define OFF_PAN 0            // 16 panels x 4KB = 64KB  (Y1 tile, ldmatrix layout)
#define OFF_B   65536        // 2 x 16KB B tiles (256 rows x 16 floats, swizzled)
#define OFF_PA  98304        // 2 x 4KB phase-1 A tiles (64 rows x 16 floats)
#define OFF_SSEG 106496      // 64 ints
#define SMEM_F  106752
// epilogue overlay: sbuf 64 x 257 floats at offset 0 (panels + PB dead by then)

// ===========================================================================
// Fused GEMM1+GEMM2 per 64-row band:
//   Phase 1: Y1 = tf32(gelu(concat(h,sf) @ Wt1^T + b1))  -> smem panels
//   Phase 2: C2 = Y1 @ Wt2^T                              (A from panels)
//   Epilogue: run-length segment-sum of (C2 + b2) -> atomics into g_sums
// 8 warps as 2x4; warp tile 32x64; BK=16; tf32 mma.sync + ldmatrix.
// ===========================================================================
__global__ __launch_bounds__(256, 2) void fused12(
    const float* __restrict__ Ah, const float* __restrict__ Asf,
    const float* __restrict__ Wt1, const float* __restrict__ b1,
    const float* __restrict__ Wt2, const float* __restrict__ b2,
    const int* __restrict__ seg, int Mrows, int K1)
{
    extern __shared__ char smem[];
    const uint32_t sbase = (uint32_t)__cvta_generic_to_shared(smem);
    float* sbuf = (float*)smem;
    int* sseg = (int*)(smem + OFF_SSEG);

    const int tid  = threadIdx.x;
    const int lane = tid & 31;
    const int warp = tid >> 5;
    const int wm   = warp >> 2;     // 0..1
    const int wn   = warp & 3;      // 0..3
    const int row0 = blockIdx.x * 64;

    const int g   = lane >> 2;
    const int tig = lane & 3;
    const int q   = lane >> 3;
    const int l8  = lane & 7;
    const int a_moff = l8 + 8 * (q & 1);
    const int a_sadd = q >> 1;
    const int b_noff = l8 + 8 * (q >> 1);
    const int b_sadd = q & 1;

    float acc[2][8][4];
#pragma unroll
    for (int i = 0; i < 2; i++)
#pragma unroll
        for (int j = 0; j < 8; j++)
#pragma unroll
            for (int k = 0; k < 4; k++) acc[i][j][k] = 0.f;

    // loader mappings
    const int am   = tid >> 2;      // phase-1 A row 0..63
    const int aslt = tid & 3;       // 16B slot
    const int bn   = tid;           // B row 0..255
    const int arow = row0 + am;
    const bool apred = (arow < Mrows);

    // ================= Phase 1: K = K1 (272) =================
    {
        const int nCh = K1 >> 4;    // 17
        float4 av, bv[4];
        // prologue
        {
            float4 v = make_float4(0.f, 0.f, 0.f, 0.f);
            if (apred) {
                const int k = aslt * 4;
                v = (k < DDIM) ? *(const float4*)(Ah + (long long)arow * DDIM + k)
                               : *(const float4*)(Asf + (long long)arow * 16 + (k - DDIM));
            }
            av = v;
#pragma unroll
            for (int s = 0; s < 4; s++)
                bv[s] = *(const float4*)(Wt1 + (long long)bn * K1 + s * 4);
        }
        int buf = 0;
        for (int t = 0; t < nCh; ++t) {
            {
                float4 v = av;
                v.x = to_tf32(v.x); v.y = to_tf32(v.y);
                v.z = to_tf32(v.z); v.w = to_tf32(v.w);
                *(float4*)(smem + OFF_PA + buf * 4096 + am * 64 +
                           16 * (aslt ^ ((am >> 1) & 3))) = v;
            }
#pragma unroll
            for (int s = 0; s < 4; s++)
                *(float4*)(smem + OFF_B + buf * 16384 + bn * 64 +
                           16 * (s ^ ((bn >> 1) & 3))) = bv[s];
            __syncthreads();

            if (t + 1 < nCh) {
                const int k0 = (t + 1) << 4;
                float4 v = make_float4(0.f, 0.f, 0.f, 0.f);
                if (apred) {
                    const int k = k0 + aslt * 4;
                    v = (k < DDIM) ? *(const float4*)(Ah + (long long)arow * DDIM + k)
                                   : *(const float4*)(Asf + (long long)arow * 16 + (k - DDIM));
                }
                av = v;
#pragma unroll
                for (int s = 0; s < 4; s++)
                    bv[s] = *(const float4*)(Wt1 + (long long)bn * K1 + k0 + s * 4);
            }

            const uint32_t Ab = sbase + OFF_PA + buf * 4096;
            const uint32_t Bb = sbase + OFF_B + buf * 16384;
#pragma unroll
            for (int ks = 0; ks < 2; ks++) {
                unsigned a[2][4];
#pragma unroll
                for (int mt = 0; mt < 2; mt++) {
                    const int m = wm * 32 + mt * 16 + a_moff;
                    const unsigned addr =
                        Ab + m * 64 + 16 * ((2 * ks + a_sadd) ^ ((a_moff >> 1) & 3));
                    ldsm4(a[mt][0], a[mt][1], a[mt][2], a[mt][3], addr);
                }
#pragma unroll
                for (int ntp = 0; ntp < 4; ntp++) {
                    const int n = wn * 64 + ntp * 16 + b_noff;
                    const unsigned addr =
                        Bb + n * 64 + 16 * ((2 * ks + b_sadd) ^ ((b_noff >> 1) & 3));
                    unsigned b0, b1x, b2x, b3;
                    ldsm4(b0, b1x, b2x, b3, addr);
                    mma_tf32(acc[0][2 * ntp], a[0], b0, b1x);
                    mma_tf32(acc[1][2 * ntp], a[1], b0, b1x);
                    mma_tf32(acc[0][2 * ntp + 1], a[0], b2x, b3);
                    mma_tf32(acc[1][2 * ntp + 1], a[1], b2x, b3);
                }
            }
            if (t + 1 < nCh) __syncthreads();
            buf ^= 1;
        }
    }

    // ---- phase-1 epilogue: gelu+bias, tf32-round, write panels ----
#pragma unroll
    for (int nt = 0; nt < 8; nt++) {
        const int c = wn * 64 + nt * 8 + tig * 2;
        const float bv0 = b1[c];
        const float bv1 = b1[c + 1];
        char* pan = smem + OFF_PAN + (c >> 4) * 4096;
        const int s = (c >> 2) & 3;
        const int o = (c & 3) * 4;
#pragma unroll
        for (int mt = 0; mt < 2; mt++) {
            const int m1 = wm * 32 + mt * 16 + g;
            float2 o1;
            o1.x = to_tf32(gelu_f(acc[mt][nt][0] + bv0));
            o1.y = to_tf32(gelu_f(acc[mt][nt][1] + bv1));
            *(float2*)(pan + m1 * 64 + 16 * (s ^ ((m1 >> 1) & 3)) + o) = o1;
            const int m2 = m1 + 8;
            float2 o2;
            o2.x = to_tf32(gelu_f(acc[mt][nt][2] + bv0));
            o2.y = to_tf32(gelu_f(acc[mt][nt][3] + bv1));
            *(float2*)(pan + m2 * 64 + 16 * (s ^ ((m2 >> 1) & 3)) + o) = o2;
        }
    }
    __syncthreads();   // panels complete; PB safe to overwrite

    // ================= Phase 2: C2 = Y1 @ Wt2^T, K = 256 =================
#pragma unroll
    for (int i = 0; i < 2; i++)
#pragma unroll
        for (int j = 0; j < 8; j++)
#pragma unroll
            for (int k = 0; k < 4; k++) acc[i][j][k] = 0.f;
    {
        const int nCh = DDIM >> 4;  // 16
        float4 bv[4];
#pragma unroll
        for (int s = 0; s < 4; s++)
            bv[s] = *(const float4*)(Wt2 + (long long)bn * DDIM + s * 4);

        int buf = 0;
        for (int t = 0; t < nCh; ++t) {
#pragma unroll
            for (int s = 0; s < 4; s++)
                *(float4*)(smem + OFF_B + buf * 16384 + bn * 64 +
                           16 * (s ^ ((bn >> 1) & 3))) = bv[s];
            __syncthreads();

            if (t + 1 < nCh) {
                const int k0 = (t + 1) << 4;
#pragma unroll
                for (int s = 0; s < 4; s++)
                    bv[s] = *(const float4*)(Wt2 + (long long)bn * DDIM + k0 + s * 4);
            }

            const uint32_t Ab = sbase + OFF_PAN + t * 4096;   // panel t
            const uint32_t Bb = sbase + OFF_B + buf * 16384;
#pragma unroll
            for (int ks = 0; ks < 2; ks++) {
                unsigned a[2][4];
#pragma unroll
                for (int mt = 0; mt < 2; mt++) {
                    const int m = wm * 32 + mt * 16 + a_moff;
                    const unsigned addr =
                        Ab + m * 64 + 16 * ((2 * ks + a_sadd) ^ ((a_moff >> 1) & 3));
                    ldsm4(a[mt][0], a[mt][1], a[mt][2], a[mt][3], addr);
                }
#pragma unroll
                for (int ntp = 0; ntp < 4; ntp++) {
                    const int n = wn * 64 + ntp * 16 + b_noff;
                    const unsigned addr =
                        Bb + n * 64 + 16 * ((2 * ks + b_sadd) ^ ((b_noff >> 1) & 3));
                    unsigned b0, b1x, b2x, b3;
                    ldsm4(b0, b1x, b2x, b3, addr);
                    mma_tf32(acc[0][2 * ntp], a[0], b0, b1x);
                    mma_tf32(acc[1][2 * ntp], a[1], b0, b1x);
                    mma_tf32(acc[0][2 * ntp + 1], a[0], b2x, b3);
                    mma_tf32(acc[1][2 * ntp + 1], a[1], b2x, b3);
                }
            }
            if (t + 1 < nCh) __syncthreads();
            buf ^= 1;
        }
    }

    // ---- epilogue: stage C2, run-length segment-sum ----
    __syncthreads();   // all panel/PB reads done before overlay
#pragma unroll
    for (int nt = 0; nt < 8; nt++) {
        const int c = wn * 64 + nt * 8 + tig * 2;
#pragma unroll
        for (int mt = 0; mt < 2; mt++) {
            const int r1 = wm * 32 + mt * 16 + g;
            sbuf[r1 * 257 + c]       = acc[mt][nt][0];
            sbuf[r1 * 257 + c + 1]   = acc[mt][nt][1];
            sbuf[(r1 + 8) * 257 + c]     = acc[mt][nt][2];
            sbuf[(r1 + 8) * 257 + c + 1] = acc[mt][nt][3];
        }
    }
    if (tid < 64) {
        const int r = row0 + tid;
        sseg[tid] = (r < Mrows) ? seg[r] : -1;
    }
    __syncthreads();
    {
        const int c = tid;
        const float bb = b2[c];
        int cur = -1;
        float run = 0.f;
        for (int r = 0; r < 64; r++) {
            const int s = sseg[r];
            if (s < 0) break;
            const float v = sbuf[r * 257 + c] + bb;
            if (s != cur) {
                if (cur >= 0) atomicAdd(&g_sums[(long long)cur * DDIM + c], run);
                cur = s;
                run = v;
            } else {
                run += v;
            }
        }
        if (cur >= 0) atomicAdd(&g_sums[(long long)cur * DDIM + c], run);
    }
}

// ===========================================================================
// GEMM3 (R3-proven MODE2 path): g_T = gelu((g_sums*inv) @ Wt3^T + bc1)
// ===========================================================================
__global__ __launch_bounds__(256, 2) void gemm3_tc(
    const float* __restrict__ Wt, const float* __restrict__ bias, int Mrows)
{
    __shared__ float4 As4[2][512];
    __shared__ float4 Bs4[2][512];

    const int tid  = threadIdx.x;
    const int lane = tid & 31;
    const int warp = tid >> 5;
    const int wm   = warp >> 1;
    const int wn   = warp & 1;
    const int row0 = blockIdx.y * 128;
    const int col0 = blockIdx.x * 128;

    const unsigned Abase = (unsigned)__cvta_generic_to_shared(&As4[0][0]);
    const unsigned Bbase = (unsigned)__cvta_generic_to_shared(&Bs4[0][0]);

    float acc[2][8][4];
#pragma unroll
    for (int i = 0; i < 2; i++)
#pragma unroll
        for (int j = 0; j < 8; j++)
#pragma unroll
            for (int k = 0; k < 4; k++) acc[i][j][k] = 0.f;

    const int am   = tid >> 2;
    const int aslt = tid & 3;
    const int bn   = tid >> 1;
    const int bs0  = (tid & 1) * 2;

    const int q  = lane >> 3;
    const int l8 = lane & 7;
    const int a_moff = l8 + 8 * (q & 1);
    const int a_sadd = q >> 1;
    const int b_noff = l8 + 8 * (q >> 1);
    const int b_sadd = q & 1;

    const int nChunks = DDIM >> 4;

    float4 av[2], bv[2];
    {
#pragma unroll
        for (int h2 = 0; h2 < 2; h2++) {
            const int m = am + 64 * h2;
            const int arow = row0 + m;
            float4 v = make_float4(0.f, 0.f, 0.f, 0.f);
            if (arow < Mrows) {
                v = *(const float4*)(g_sums + (long long)arow * DDIM + aslt * 4);
                const float sc = g_inv[arow];
                v.x *= sc; v.y *= sc; v.z *= sc; v.w *= sc;
            }
            av[h2] = v;
        }
#pragma unroll
        for (int s = 0; s < 2; s++)
            bv[s] = *(const float4*)(Wt + (long long)(col0 + bn) * DDIM + (bs0 + s) * 4);
    }

    int buf = 0;
    for (int t = 0; t < nChunks; ++t) {
#pragma unroll
        for (int h2 = 0; h2 < 2; h2++) {
            const int m = am + 64 * h2;
            float4 v = av[h2];
            v.x = to_tf32(v.x); v.y = to_tf32(v.y);
            v.z = to_tf32(v.z); v.w = to_tf32(v.w);
            As4[buf][(m * 64 + 16 * (aslt ^ ((m >> 1) & 3))) >> 4] = v;
        }
#pragma unroll
        for (int s = 0; s < 2; s++) {
            const int slot = bs0 + s;
            Bs4[buf][(bn * 64 + 16 * (slot ^ ((bn >> 1) & 3))) >> 4] = bv[s];
        }
        __syncthreads();

        if (t + 1 < nChunks) {
            const int k0 = (t + 1) << 4;
#pragma unroll
            for (int h2 = 0; h2 < 2; h2++) {
                const int m = am + 64 * h2;
                const int arow = row0 + m;
                float4 v = make_float4(0.f, 0.f, 0.f, 0.f);
                if (arow < Mrows) {
                    v = *(const float4*)(g_sums + (long long)arow * DDIM + k0 + aslt * 4);
                    const float sc = g_inv[arow];
                    v.x *= sc; v.y *= sc; v.z *= sc; v.w *= sc;
                }
                av[h2] = v;
            }
#pragma unroll
            for (int s = 0; s < 2; s++)
                bv[s] = *(const float4*)(Wt + (long long)(col0 + bn) * DDIM + k0 + (bs0 + s) * 4);
        }

        const unsigned Ab = Abase + buf * 8192;
        const unsigned Bb = Bbase + buf * 8192;
#pragma unroll
        for (int ks = 0; ks < 2; ks++) {
            unsigned a[2][4];
#pragma unroll
            for (int mt = 0; mt < 2; mt++) {
                const int m = wm * 32 + mt * 16 + a_moff;
                const unsigned addr = Ab + m * 64 + 16 * ((2 * ks + a_sadd) ^ ((a_moff >> 1) & 3));
                ldsm4(a[mt][0], a[mt][1], a[mt][2], a[mt][3], addr);
            }
#pragma unroll
            for (int ntp = 0; ntp < 4; ntp++) {
                const int n = wn * 64 + ntp * 16 + b_noff;
                const unsigned addr = Bb + n * 64 + 16 * ((2 * ks + b_sadd) ^ ((b_noff >> 1) & 3));
                unsigned b0, b1, b2, b3;
                ldsm4(b0, b1, b2, b3, addr);
                mma_tf32(acc[0][2 * ntp], a[0], b0, b1);
                mma_tf32(acc[1][2 * ntp], a[1], b0, b1);
                mma_tf32(acc[0][2 * ntp + 1], a[0], b2, b3);
                mma_tf32(acc[1][2 * ntp + 1], a[1], b2, b3);
            }
        }
        if (t + 1 < nChunks) __syncthreads();
        buf ^= 1;
    }

    const int g   = lane >> 2;
    const int tig = lane & 3;
#pragma unroll
    for (int nt = 0; nt < 8; nt++) {
        const int c = col0 + wn * 64 + nt * 8 + tig * 2;
        const float bv0 = bias[c];
        const float bv1 = bias[c + 1];
#pragma unroll
        for (int mt = 0; mt < 2; mt++) {
            const int r1 = row0 + wm * 32 + mt * 16 + g;
            if (r1 < Mrows) {
                float2 o;
                o.x = gelu_f(acc[mt][nt][0] + bv0);
                o.y = gelu_f(acc[mt][nt][1] + bv1);
                *(float2*)(g_T + (long long)r1 * DDIM + c) = o;
            }
            const int r2 = r1 + 8;
            if (r2 < Mrows) {
                float2 o;
                o.x = gelu_f(acc[mt][nt][2] + bv0);
                o.y = gelu_f(acc[mt][nt][3] + bv1);
                *(float2*)(g_T + (long long)r2 * DDIM + c) = o;
            }
        }
    }
}

// ---------------------------------------------------------------------------
__global__ void prep_w(const float* __restrict__ W, float* __restrict__ Wt, int K) {
    const int idx = blockIdx.x * blockDim.x + threadIdx.x;
    if (idx < K * DDIM) {
        const int k = idx / DDIM, n = idx % DDIM;
        Wt[n * K + k] = to_tf32(W[idx]);
    }
}

__global__ void zero_kernel(int G) {
    const long long total = (long long)G * DDIM;
    const long long stride = (long long)gridDim.x * blockDim.x;
    for (long long i = (long long)blockIdx.x * blockDim.x + threadIdx.x; i < total; i += stride)
        g_sums[i] = 0.f;
    for (long long i = (long long)blockIdx.x * blockDim.x + threadIdx.x; i < G; i += stride)
        g_cnt[i] = 0.f;
}

__global__ void count_kernel(const int* __restrict__ seg, int N) {
    const int i = blockIdx.x * blockDim.x + threadIdx.x;
    if (i < N) atomicAdd(&g_cnt[seg[i]], 1.0f);
}

__global__ void inv_kernel(int G) {
    const int i = blockIdx.x * blockDim.x + threadIdx.x;
    if (i < G) g_inv[i] = 1.0f / fmaxf(g_cnt[i], 1.0f);
}

__global__ __launch_bounds__(128) void head_kernel(
    const float* __restrict__ Wc2, const float* __restrict__ bc2,
    float* __restrict__ out, int G)
{
    __shared__ float sW[DDIM * CDIM];
    __shared__ float sb[CDIM];
    const int tid = threadIdx.x;
    for (int i = tid; i < DDIM * CDIM; i += 128) sW[i] = Wc2[i];
    if (tid < CDIM) sb[tid] = bc2[tid];
    __syncthreads();

    const int warp = tid >> 5;
    const int lane = tid & 31;
    const int g = blockIdx.x * 4 + warp;
    if (g >= G) return;

    const float* t = g_T + (long long)g * DDIM;
    const float4 v0 = *(const float4*)(t + lane * 8);
    const float4 v1 = *(const float4*)(t + lane * 8 + 4);
    const float tv[8] = {v0.x, v0.y, v0.z, v0.w, v1.x, v1.y, v1.z, v1.w};

    float acc[CDIM];
#pragma unroll
    for (int c = 0; c < CDIM; c++) acc[c] = 0.f;
#pragma unroll
    for (int u = 0; u < 8; u++) {
        const float* w = &sW[(lane * 8 + u) * CDIM];
#pragma unroll
        for (int c = 0; c < CDIM; c++) acc[c] += tv[u] * w[c];
    }
#pragma unroll
    for (int off = 16; off > 0; off >>= 1)
#pragma unroll
        for (int c = 0; c < CDIM; c++) acc[c] += __shfl_down_sync(0xffffffffu, acc[c], off);

    if (lane == 0) {
#pragma unroll
        for (int c = 0; c < CDIM; c++) out[(long long)g * CDIM + c] = acc[c] + sb[c];
    }
}

// ---------------------------------------------------------------------------
extern "C" void kernel_launch(void* const* d_in, const int* in_sizes, int n_in,
                              void* d_out, int out_size)
{
    const float* h   = (const float*)d_in[0];
    const float* sf  = (const float*)d_in[1];
    const float* W1a = (const float*)d_in[2];
    const float* b1a = (const float*)d_in[3];
    const float* W2a = (const float*)d_in[4];
    const float* b2a = (const float*)d_in[5];
    const float* Wc1 = (const float*)d_in[6];
    const float* bc1 = (const float*)d_in[7];
    const float* Wc2 = (const float*)d_in[8];
    const float* bc2 = (const float*)d_in[9];
    const int* seg   = (const int*)d_in[10];
    float* out = (float*)d_out;

    const int D = in_sizes[3];
    const int N = in_sizes[0] / D;
    const int C = in_sizes[8] / D;
    const int G = out_size / C;
    const int K1 = D + in_sizes[1] / N;   // 272

    float* wt1; cudaGetSymbolAddress((void**)&wt1, g_Wt1);
    float* wt2; cudaGetSymbolAddress((void**)&wt2, g_Wt2);
    float* wt3; cudaGetSymbolAddress((void**)&wt3, g_Wt3);

    cudaFuncSetAttribute(fused12, cudaFuncAttributeMaxDynamicSharedMemorySize, SMEM_F);

    prep_w<<<(K1 * D + 255) / 256, 256>>>(W1a, wt1, K1);
    prep_w<<<(D * D + 255) / 256, 256>>>(W2a, wt2, D);
    prep_w<<<(D * D + 255) / 256, 256>>>(Wc1, wt3, D);
    zero_kernel<<<2048, 256>>>(G);
    count_kernel<<<(N + 255) / 256, 256>>>(seg, N);
    fused12<<<(N + 63) / 64, 256, SMEM_F>>>(h, sf, wt1, b1a, wt2, b2a, seg, N, K1);
    inv_kernel<<<(G + 255) / 256, 256>>>(G);
    gemm3_tc<<<dim3(2, (G + 127) / 128), 256>>>(wt3, bc1, G);
    head_kernel<<<(G + 3) / 4, 128>>>(Wc2, bc2, out, G);
}

// round 7
// speedup vs baseline: 1.6442x; 1.4105x over previous
#include <cuda_runtime.h>
#include <math.h>
#include <stdint.h>

#define DDIM 256
#define CDIM 10
#define MAXN 500000
#define MAXG 100000

__device__ float g_sums[(long long)MAXG * DDIM];
__device__ float g_cnt[MAXG];
__device__ float g_inv[MAXG];
__device__ float g_T[(long long)MAXG * DDIM];
__device__ float g_Wt1[DDIM * 272];   // Wt[n][k] tf32-rounded
__device__ float g_Wt2[DDIM * DDIM];
__device__ float g_Wt3[DDIM * DDIM];

__device__ __forceinline__ float gelu_f(float x) {
    return 0.5f * x * (1.0f + erff(x * 0.70710678118654752f));
}
__device__ __forceinline__ float to_tf32(float x) {
    float r;
    asm("cvt.rna.tf32.f32 %0, %1;" : "=f"(r) : "f"(x));
    return r;
}
__device__ __forceinline__ void mma_tf32(float c[4], const unsigned a[4],
                                         unsigned b0, unsigned b1) {
    asm volatile(
        "mma.sync.aligned.m16n8k8.row.col.f32.tf32.tf32.f32 "
        "{%0,%1,%2,%3},{%4,%5,%6,%7},{%8,%9},{%0,%1,%2,%3};"
        : "+f"(c[0]), "+f"(c[1]), "+f"(c[2]), "+f"(c[3])
        : "r"(a[0]), "r"(a[1]), "r"(a[2]), "r"(a[3]), "r"(b0), "r"(b1));
}
__device__ __forceinline__ void ldsm4(unsigned &d0, unsigned &d1, unsigned &d2,
                                      unsigned &d3, unsigned addr) {
    asm volatile("ldmatrix.sync.aligned.m8n8.x4.shared.b16 {%0,%1,%2,%3}, [%4];"
                 : "=r"(d0), "=r"(d1), "=r"(d2), "=r"(d3) : "r"(addr));
}

// ---- fused-128 smem layout (bytes) ----
#define OFF_PAN 0            // 16 panels x 8KB = 128KB (Y1 tile, ldmatrix layout)
#define OFF_B   131072       // 2 x 16KB B tiles (256 rows x 16 floats, swizzled)
#define OFF_PA  163840       // 2 x 8KB phase-1 A tiles (128 rows x 16 floats)
#define OFF_SSEG 180224      // 128 ints
#define SMEM_F  180736
// epilogue overlay: sbuf 128 x 257 floats at offset 0 (panels dead by then)

// ===========================================================================
// Fused GEMM1+GEMM2 per 128-row band, 512 threads (16 warps as 4x4):
//   Phase 1: Y1 = tf32(gelu(concat(h,sf) @ Wt1^T + b1))  -> smem panels
//   Phase 2: C2 = Y1 @ Wt2^T                              (A from panels)
//   Epilogue: run-length segment-sum of (C2 + b2) -> atomics into g_sums
// ===========================================================================
__global__ __launch_bounds__(512, 1) void fused12(
    const float* __restrict__ Ah, const float* __restrict__ Asf,
    const float* __restrict__ Wt1, const float* __restrict__ b1,
    const float* __restrict__ Wt2, const float* __restrict__ b2,
    const int* __restrict__ seg, int Mrows, int K1)
{
    extern __shared__ char smem[];
    const uint32_t sbase = (uint32_t)__cvta_generic_to_shared(smem);
    float* sbuf = (float*)smem;
    int* sseg = (int*)(smem + OFF_SSEG);

    const int tid  = threadIdx.x;
    const int lane = tid & 31;
    const int warp = tid >> 5;
    const int wm   = warp >> 2;     // 0..3
    const int wn   = warp & 3;      // 0..3
    const int row0 = blockIdx.x * 128;

    const int g   = lane >> 2;
    const int tig = lane & 3;
    const int q   = lane >> 3;
    const int l8  = lane & 7;
    const int a_moff = l8 + 8 * (q & 1);
    const int a_sadd = q >> 1;
    const int b_noff = l8 + 8 * (q >> 1);
    const int b_sadd = q & 1;

    float acc[2][8][4];
#pragma unroll
    for (int i = 0; i < 2; i++)
#pragma unroll
        for (int j = 0; j < 8; j++)
#pragma unroll
            for (int k = 0; k < 4; k++) acc[i][j][k] = 0.f;

    // loader mappings (512 threads)
    const int am   = tid >> 2;        // A row 0..127
    const int aslt = tid & 3;         // 16B slot 0..3
    const int bn   = tid >> 1;        // B row 0..255
    const int ls0  = (tid & 1) * 2;   // slots {ls0, ls0+1}
    const int arow = row0 + am;
    const bool apred = (arow < Mrows);

    // ================= Phase 1: K = K1 (272) =================
    {
        const int nCh = K1 >> 4;    // 17
        float4 av, bv[2];
        {
            float4 v = make_float4(0.f, 0.f, 0.f, 0.f);
            if (apred) {
                const int k = aslt * 4;
                v = (k < DDIM) ? *(const float4*)(Ah + (long long)arow * DDIM + k)
                               : *(const float4*)(Asf + (long long)arow * 16 + (k - DDIM));
            }
            av = v;
#pragma unroll
            for (int s = 0; s < 2; s++)
                bv[s] = *(const float4*)(Wt1 + (long long)bn * K1 + (ls0 + s) * 4);
        }
        int buf = 0;
        for (int t = 0; t < nCh; ++t) {
            {
                float4 v = av;
                v.x = to_tf32(v.x); v.y = to_tf32(v.y);
                v.z = to_tf32(v.z); v.w = to_tf32(v.w);
                *(float4*)(smem + OFF_PA + buf * 8192 + am * 64 +
                           16 * (aslt ^ ((am >> 1) & 3))) = v;
            }
#pragma unroll
            for (int s = 0; s < 2; s++) {
                const int slot = ls0 + s;
                *(float4*)(smem + OFF_B + buf * 16384 + bn * 64 +
                           16 * (slot ^ ((bn >> 1) & 3))) = bv[s];
            }
            __syncthreads();

            if (t + 1 < nCh) {
                const int k0 = (t + 1) << 4;
                float4 v = make_float4(0.f, 0.f, 0.f, 0.f);
                if (apred) {
                    const int k = k0 + aslt * 4;
                    v = (k < DDIM) ? *(const float4*)(Ah + (long long)arow * DDIM + k)
                                   : *(const float4*)(Asf + (long long)arow * 16 + (k - DDIM));
                }
                av = v;
#pragma unroll
                for (int s = 0; s < 2; s++)
                    bv[s] = *(const float4*)(Wt1 + (long long)bn * K1 + k0 + (ls0 + s) * 4);
            }

            const uint32_t Ab = sbase + OFF_PA + buf * 8192;
            const uint32_t Bb = sbase + OFF_B + buf * 16384;
#pragma unroll
            for (int ks = 0; ks < 2; ks++) {
                unsigned a[2][4];
#pragma unroll
                for (int mt = 0; mt < 2; mt++) {
                    const int m = wm * 32 + mt * 16 + a_moff;
                    const unsigned addr =
                        Ab + m * 64 + 16 * ((2 * ks + a_sadd) ^ ((a_moff >> 1) & 3));
                    ldsm4(a[mt][0], a[mt][1], a[mt][2], a[mt][3], addr);
                }
#pragma unroll
                for (int ntp = 0; ntp < 4; ntp++) {
                    const int n = wn * 64 + ntp * 16 + b_noff;
                    const unsigned addr =
                        Bb + n * 64 + 16 * ((2 * ks + b_sadd) ^ ((b_noff >> 1) & 3));
                    unsigned b0, b1x, b2x, b3;
                    ldsm4(b0, b1x, b2x, b3, addr);
                    mma_tf32(acc[0][2 * ntp], a[0], b0, b1x);
                    mma_tf32(acc[1][2 * ntp], a[1], b0, b1x);
                    mma_tf32(acc[0][2 * ntp + 1], a[0], b2x, b3);
                    mma_tf32(acc[1][2 * ntp + 1], a[1], b2x, b3);
                }
            }
            if (t + 1 < nCh) __syncthreads();
            buf ^= 1;
        }
    }

    // ---- phase-1 epilogue: gelu+bias, tf32-round, write panels ----
#pragma unroll
    for (int nt = 0; nt < 8; nt++) {
        const int c = wn * 64 + nt * 8 + tig * 2;
        const float bv0 = b1[c];
        const float bv1 = b1[c + 1];
        char* pan = smem + OFF_PAN + (c >> 4) * 8192;
        const int s = (c >> 2) & 3;
        const int o = (c & 3) * 4;
#pragma unroll
        for (int mt = 0; mt < 2; mt++) {
            const int m1 = wm * 32 + mt * 16 + g;
            float2 o1;
            o1.x = to_tf32(gelu_f(acc[mt][nt][0] + bv0));
            o1.y = to_tf32(gelu_f(acc[mt][nt][1] + bv1));
            *(float2*)(pan + m1 * 64 + 16 * (s ^ ((m1 >> 1) & 3)) + o) = o1;
            const int m2 = m1 + 8;
            float2 o2;
            o2.x = to_tf32(gelu_f(acc[mt][nt][2] + bv0));
            o2.y = to_tf32(gelu_f(acc[mt][nt][3] + bv1));
            *(float2*)(pan + m2 * 64 + 16 * (s ^ ((m2 >> 1) & 3)) + o) = o2;
        }
    }
    __syncthreads();   // panels complete; B buffers free

    // ================= Phase 2: C2 = Y1 @ Wt2^T, K = 256 =================
#pragma unroll
    for (int i = 0; i < 2; i++)
#pragma unroll
        for (int j = 0; j < 8; j++)
#pragma unroll
            for (int k = 0; k < 4; k++) acc[i][j][k] = 0.f;
    {
        const int nCh = DDIM >> 4;  // 16
        float4 bv[2];
#pragma unroll
        for (int s = 0; s < 2; s++)
            bv[s] = *(const float4*)(Wt2 + (long long)bn * DDIM + (ls0 + s) * 4);

        int buf = 0;
        for (int t = 0; t < nCh; ++t) {
#pragma unroll
            for (int s = 0; s < 2; s++) {
                const int slot = ls0 + s;
                *(float4*)(smem + OFF_B + buf * 16384 + bn * 64 +
                           16 * (slot ^ ((bn >> 1) & 3))) = bv[s];
            }
            __syncthreads();

            if (t + 1 < nCh) {
                const int k0 = (t + 1) << 4;
#pragma unroll
                for (int s = 0; s < 2; s++)
                    bv[s] = *(const float4*)(Wt2 + (long long)bn * DDIM + k0 + (ls0 + s) * 4);
            }

            const uint32_t Ab = sbase + OFF_PAN + t * 8192;   // panel t
            const uint32_t Bb = sbase + OFF_B + buf * 16384;
#pragma unroll
            for (int ks = 0; ks < 2; ks++) {
                unsigned a[2][4];
#pragma unroll
                for (int mt = 0; mt < 2; mt++) {
                    const int m = wm * 32 + mt * 16 + a_moff;
                    const unsigned addr =
                        Ab + m * 64 + 16 * ((2 * ks + a_sadd) ^ ((a_moff >> 1) & 3));
                    ldsm4(a[mt][0], a[mt][1], a[mt][2], a[mt][3], addr);
                }
#pragma unroll
                for (int ntp = 0; ntp < 4; ntp++) {
                    const int n = wn * 64 + ntp * 16 + b_noff;
                    const unsigned addr =
                        Bb + n * 64 + 16 * ((2 * ks + b_sadd) ^ ((b_noff >> 1) & 3));
                    unsigned b0, b1x, b2x, b3;
                    ldsm4(b0, b1x, b2x, b3, addr);
                    mma_tf32(acc[0][2 * ntp], a[0], b0, b1x);
                    mma_tf32(acc[1][2 * ntp], a[1], b0, b1x);
                    mma_tf32(acc[0][2 * ntp + 1], a[0], b2x, b3);
                    mma_tf32(acc[1][2 * ntp + 1], a[1], b2x, b3);
                }
            }
            if (t + 1 < nCh) __syncthreads();
            buf ^= 1;
        }
    }

    // ---- epilogue: stage C2, run-length segment-sum ----
    __syncthreads();   // all panel reads done before overlay
#pragma unroll
    for (int nt = 0; nt < 8; nt++) {
        const int c = wn * 64 + nt * 8 + tig * 2;
#pragma unroll
        for (int mt = 0; mt < 2; mt++) {
            const int r1 = wm * 32 + mt * 16 + g;
            sbuf[r1 * 257 + c]           = acc[mt][nt][0];
            sbuf[r1 * 257 + c + 1]       = acc[mt][nt][1];
            sbuf[(r1 + 8) * 257 + c]     = acc[mt][nt][2];
            sbuf[(r1 + 8) * 257 + c + 1] = acc[mt][nt][3];
        }
    }
    if (tid < 128) {
        const int r = row0 + tid;
        sseg[tid] = (r < Mrows) ? seg[r] : -1;
    }
    __syncthreads();
    {
        const int c = tid & 255;
        const int rbeg = (tid >> 8) * 64;
        const float bb = b2[c];
        int cur = -1;
        float run = 0.f;
        for (int r = rbeg; r < rbeg + 64; r++) {
            const int s = sseg[r];
            if (s < 0) break;
            const float v = sbuf[r * 257 + c] + bb;
            if (s != cur) {
                if (cur >= 0) atomicAdd(&g_sums[(long long)cur * DDIM + c], run);
                cur = s;
                run = v;
            } else {
                run += v;
            }
        }
        if (cur >= 0) atomicAdd(&g_sums[(long long)cur * DDIM + c], run);
    }
}

// ===========================================================================
// GEMM3 (R3-proven MODE2 path): g_T = gelu((g_sums*inv) @ Wt3^T + bc1)
// ===========================================================================
__global__ __launch_bounds__(256, 2) void gemm3_tc(
    const float* __restrict__ Wt, const float* __restrict__ bias, int Mrows)
{
    __shared__ float4 As4[2][512];
    __shared__ float4 Bs4[2][512];

    const int tid  = threadIdx.x;
    const int lane = tid & 31;
    const int warp = tid >> 5;
    const int wm   = warp >> 1;
    const int wn   = warp & 1;
    const int row0 = blockIdx.y * 128;
    const int col0 = blockIdx.x * 128;

    const unsigned Abase = (unsigned)__cvta_generic_to_shared(&As4[0][0]);
    const unsigned Bbase = (unsigned)__cvta_generic_to_shared(&Bs4[0][0]);

    float acc[2][8][4];
#pragma unroll
    for (int i = 0; i < 2; i++)
#pragma unroll
        for (int j = 0; j < 8; j++)
#pragma unroll
            for (int k = 0; k < 4; k++) acc[i][j][k] = 0.f;

    const int am   = tid >> 2;
    const int aslt = tid & 3;
    const int bn   = tid >> 1;
    const int bs0  = (tid & 1) * 2;

    const int q  = lane >> 3;
    const int l8 = lane & 7;
    const int a_moff = l8 + 8 * (q & 1);
    const int a_sadd = q >> 1;
    const int b_noff = l8 + 8 * (q >> 1);
    const int b_sadd = q & 1;

    const int nChunks = DDIM >> 4;

    float4 av[2], bv[2];
    {
#pragma unroll
        for (int h2 = 0; h2 < 2; h2++) {
            const int m = am + 64 * h2;
            const int arow = row0 + m;
            float4 v = make_float4(0.f, 0.f, 0.f, 0.f);
            if (arow < Mrows) {
                v = *(const float4*)(g_sums + (long long)arow * DDIM + aslt * 4);
                const float sc = g_inv[arow];
                v.x *= sc; v.y *= sc; v.z *= sc; v.w *= sc;
            }
            av[h2] = v;
        }
#pragma unroll
        for (int s = 0; s < 2; s++)
            bv[s] = *(const float4*)(Wt + (long long)(col0 + bn) * DDIM + (bs0 + s) * 4);
    }

    int buf = 0;
    for (int t = 0; t < nChunks; ++t) {
#pragma unroll
        for (int h2 = 0; h2 < 2; h2++) {
            const int m = am + 64 * h2;
            float4 v = av[h2];
            v.x = to_tf32(v.x); v.y = to_tf32(v.y);
            v.z = to_tf32(v.z); v.w = to_tf32(v.w);
            As4[buf][(m * 64 + 16 * (aslt ^ ((m >> 1) & 3))) >> 4] = v;
        }
#pragma unroll
        for (int s = 0; s < 2; s++) {
            const int slot = bs0 + s;
            Bs4[buf][(bn * 64 + 16 * (slot ^ ((bn >> 1) & 3))) >> 4] = bv[s];
        }
        __syncthreads();

        if (t + 1 < nChunks) {
            const int k0 = (t + 1) << 4;
#pragma unroll
            for (int h2 = 0; h2 < 2; h2++) {
                const int m = am + 64 * h2;
                const int arow = row0 + m;
                float4 v = make_float4(0.f, 0.f, 0.f, 0.f);
                if (arow < Mrows) {
                    v = *(const float4*)(g_sums + (long long)arow * DDIM + k0 + aslt * 4);
                    const float sc = g_inv[arow];
                    v.x *= sc; v.y *= sc; v.z *= sc; v.w *= sc;
                }
                av[h2] = v;
            }
#pragma unroll
            for (int s = 0; s < 2; s++)
                bv[s] = *(const float4*)(Wt + (long long)(col0 + bn) * DDIM + k0 + (bs0 + s) * 4);
        }

        const unsigned Ab = Abase + buf * 8192;
        const unsigned Bb = Bbase + buf * 8192;
#pragma unroll
        for (int ks = 0; ks < 2; ks++) {
            unsigned a[2][4];
#pragma unroll
            for (int mt = 0; mt < 2; mt++) {
                const int m = wm * 32 + mt * 16 + a_moff;
                const unsigned addr = Ab + m * 64 + 16 * ((2 * ks + a_sadd) ^ ((a_moff >> 1) & 3));
                ldsm4(a[mt][0], a[mt][1], a[mt][2], a[mt][3], addr);
            }
#pragma unroll
            for (int ntp = 0; ntp < 4; ntp++) {
                const int n = wn * 64 + ntp * 16 + b_noff;
                const unsigned addr = Bb + n * 64 + 16 * ((2 * ks + b_sadd) ^ ((b_noff >> 1) & 3));
                unsigned b0, b1, b2, b3;
                ldsm4(b0, b1, b2, b3, addr);
                mma_tf32(acc[0][2 * ntp], a[0], b0, b1);
                mma_tf32(acc[1][2 * ntp], a[1], b0, b1);
                mma_tf32(acc[0][2 * ntp + 1], a[0], b2, b3);
                mma_tf32(acc[1][2 * ntp + 1], a[1], b2, b3);
            }
        }
        if (t + 1 < nChunks) __syncthreads();
        buf ^= 1;
    }

    const int g   = lane >> 2;
    const int tig = lane & 3;
#pragma unroll
    for (int nt = 0; nt < 8; nt++) {
        const int c = col0 + wn * 64 + nt * 8 + tig * 2;
        const float bv0 = bias[c];
        const float bv1 = bias[c + 1];
#pragma unroll
        for (int mt = 0; mt < 2; mt++) {
            const int r1 = row0 + wm * 32 + mt * 16 + g;
            if (r1 < Mrows) {
                float2 o;
                o.x = gelu_f(acc[mt][nt][0] + bv0);
                o.y = gelu_f(acc[mt][nt][1] + bv1);
                *(float2*)(g_T + (long long)r1 * DDIM + c) = o;
            }
            const int r2 = r1 + 8;
            if (r2 < Mrows) {
                float2 o;
                o.x = gelu_f(acc[mt][nt][2] + bv0);
                o.y = gelu_f(acc[mt][nt][3] + bv1);
                *(float2*)(g_T + (long long)r2 * DDIM + c) = o;
            }
        }
    }
}

// ---------------------------------------------------------------------------
__global__ void prep_w(const float* __restrict__ W, float* __restrict__ Wt, int K) {
    const int idx = blockIdx.x * blockDim.x + threadIdx.x;
    if (idx < K * DDIM) {
        const int k = idx / DDIM, n = idx % DDIM;
        Wt[n * K + k] = to_tf32(W[idx]);
    }
}

__global__ void zero_kernel(int G) {
    const long long total = (long long)G * DDIM;
    const long long stride = (long long)gridDim.x * blockDim.x;
    for (long long i = (long long)blockIdx.x * blockDim.x + threadIdx.x; i < total; i += stride)
        g_sums[i] = 0.f;
    for (long long i = (long long)blockIdx.x * blockDim.x + threadIdx.x; i < G; i += stride)
        g_cnt[i] = 0.f;
}

__global__ void count_kernel(const int* __restrict__ seg, int N) {
    const int i = blockIdx.x * blockDim.x + threadIdx.x;
    if (i < N) atomicAdd(&g_cnt[seg[i]], 1.0f);
}

__global__ void inv_kernel(int G) {
    const int i = blockIdx.x * blockDim.x + threadIdx.x;
    if (i < G) g_inv[i] = 1.0f / fmaxf(g_cnt[i], 1.0f);
}

__global__ __launch_bounds__(128) void head_kernel(
    const float* __restrict__ Wc2, const float* __restrict__ bc2,
    float* __restrict__ out, int G)
{
    __shared__ float sW[DDIM * CDIM];
    __shared__ float sb[CDIM];
    const int tid = threadIdx.x;
    for (int i = tid; i < DDIM * CDIM; i += 128) sW[i] = Wc2[i];
    if (tid < CDIM) sb[tid] = bc2[tid];
    __syncthreads();

    const int warp = tid >> 5;
    const int lane = tid & 31;
    const int g = blockIdx.x * 4 + warp;
    if (g >= G) return;

    const float* t = g_T + (long long)g * DDIM;
    const float4 v0 = *(const float4*)(t + lane * 8);
    const float4 v1 = *(const float4*)(t + lane * 8 + 4);
    const float tv[8] = {v0.x, v0.y, v0.z, v0.w, v1.x, v1.y, v1.z, v1.w};

    float acc[CDIM];
#pragma unroll
    for (int c = 0; c < CDIM; c++) acc[c] = 0.f;
#pragma unroll
    for (int u = 0; u < 8; u++) {
        const float* w = &sW[(lane * 8 + u) * CDIM];
#pragma unroll
        for (int c = 0; c < CDIM; c++) acc[c] += tv[u] * w[c];
    }
#pragma unroll
    for (int off = 16; off > 0; off >>= 1)
#pragma unroll
        for (int c = 0; c < CDIM; c++) acc[c] += __shfl_down_sync(0xffffffffu, acc[c], off);

    if (lane == 0) {
#pragma unroll
        for (int c = 0; c < CDIM; c++) out[(long long)g * CDIM + c] = acc[c] + sb[c];
    }
}

// ---------------------------------------------------------------------------
extern "C" void kernel_launch(void* const* d_in, const int* in_sizes, int n_in,
                              void* d_out, int out_size)
{
    const float* h   = (const float*)d_in[0];
    const float* sf  = (const float*)d_in[1];
    const float* W1a = (const float*)d_in[2];
    const float* b1a = (const float*)d_in[3];
    const float* W2a = (const float*)d_in[4];
    const float* b2a = (const float*)d_in[5];
    const float* Wc1 = (const float*)d_in[6];
    const float* bc1 = (const float*)d_in[7];
    const float* Wc2 = (const float*)d_in[8];
    const float* bc2 = (const float*)d_in[9];
    const int* seg   = (const int*)d_in[10];
    float* out = (float*)d_out;

    const int D = in_sizes[3];
    const int N = in_sizes[0] / D;
    const int C = in_sizes[8] / D;
    const int G = out_size / C;
    const int K1 = D + in_sizes[1] / N;   // 272

    float* wt1; cudaGetSymbolAddress((void**)&wt1, g_Wt1);
    float* wt2; cudaGetSymbolAddress((void**)&wt2, g_Wt2);
    float* wt3; cudaGetSymbolAddress((void**)&wt3, g_Wt3);

    cudaFuncSetAttribute(fused12, cudaFuncAttributeMaxDynamicSharedMemorySize, SMEM_F);

    prep_w<<<(K1 * D + 255) / 256, 256>>>(W1a, wt1, K1);
    prep_w<<<(D * D + 255) / 256, 256>>>(W2a, wt2, D);
    prep_w<<<(D * D + 255) / 256, 256>>>(Wc1, wt3, D);
    zero_kernel<<<2048, 256>>>(G);
    count_kernel<<<(N + 255) / 256, 256>>>(seg, N);
    fused12<<<(N + 127) / 128, 512, SMEM_F>>>(h, sf, wt1, b1a, wt2, b2a, seg, N, K1);
    inv_kernel<<<(G + 255) / 256, 256>>>(G);
    gemm3_tc<<<dim3(2, (G + 127) / 128), 256>>>(wt3, bc1, G);
    head_kernel<<<(G + 3) / 4, 128>>>(Wc2, bc2, out, G);
}

// round 8
// speedup vs baseline: 1.6487x; 1.0028x over previous
#include <cuda_runtime.h>
#include <math.h>
#include <stdint.h>

#define DDIM 256
#define CDIM 10
#define MAXN 500000
#define MAXG 100000

__device__ float g_sums[(long long)MAXG * DDIM];
__device__ float g_cnt[MAXG];
__device__ float g_inv[MAXG];
__device__ float g_T[(long long)MAXG * DDIM];
__device__ float g_Wt1[DDIM * 272];   // Wt[n][k] tf32-rounded
__device__ float g_Wt2[DDIM * DDIM];
__device__ float g_Wt3[DDIM * DDIM];

__device__ __forceinline__ float gelu_f(float x) {
    return 0.5f * x * (1.0f + erff(x * 0.70710678118654752f));
}
__device__ __forceinline__ float to_tf32(float x) {
    float r;
    asm("cvt.rna.tf32.f32 %0, %1;" : "=f"(r) : "f"(x));
    return r;
}
__device__ __forceinline__ void mma_tf32(float c[4], const unsigned a[4],
                                         unsigned b0, unsigned b1) {
    asm volatile(
        "mma.sync.aligned.m16n8k8.row.col.f32.tf32.tf32.f32 "
        "{%0,%1,%2,%3},{%4,%5,%6,%7},{%8,%9},{%0,%1,%2,%3};"
        : "+f"(c[0]), "+f"(c[1]), "+f"(c[2]), "+f"(c[3])
        : "r"(a[0]), "r"(a[1]), "r"(a[2]), "r"(a[3]), "r"(b0), "r"(b1));
}
__device__ __forceinline__ void ldsm4(unsigned &d0, unsigned &d1, unsigned &d2,
                                      unsigned &d3, unsigned addr) {
    asm volatile("ldmatrix.sync.aligned.m8n8.x4.shared.b16 {%0,%1,%2,%3}, [%4];"
                 : "=r"(d0), "=r"(d1), "=r"(d2), "=r"(d3) : "r"(addr));
}

// ---- fused-128 smem layout (bytes) ----
#define OFF_PAN 0            // 16 panels x 8KB = 128KB (Y1 tile, ldmatrix layout)
#define OFF_B   131072       // 2 x 16KB B tiles (256 rows x 16 floats, swizzled)
#define OFF_PA  163840       // 2 x 8KB phase-1 A tiles (128 rows x 16 floats)
#define OFF_SSEG 180224      // 128 ints
#define SMEM_F  180736
// epilogue overlay: sbuf 128 x 257 floats at offset 0 (panels dead by then)

// ===========================================================================
// Fused GEMM1+GEMM2 per 128-row band, 512 threads (16 warps as 4x4).
// Single-__syncthreads-per-chunk double buffering:
//   prefetch(t+1) -> compute(buf) -> store(->buf^1) -> sync
// ===========================================================================
__global__ __launch_bounds__(512, 1) void fused12(
    const float* __restrict__ Ah, const float* __restrict__ Asf,
    const float* __restrict__ Wt1, const float* __restrict__ b1,
    const float* __restrict__ Wt2, const float* __restrict__ b2,
    const int* __restrict__ seg, int Mrows, int K1)
{
    extern __shared__ char smem[];
    const uint32_t sbase = (uint32_t)__cvta_generic_to_shared(smem);
    float* sbuf = (float*)smem;
    int* sseg = (int*)(smem + OFF_SSEG);

    const int tid  = threadIdx.x;
    const int lane = tid & 31;
    const int warp = tid >> 5;
    const int wm   = warp >> 2;     // 0..3
    const int wn   = warp & 3;      // 0..3
    const int row0 = blockIdx.x * 128;

    const int g   = lane >> 2;
    const int tig = lane & 3;
    const int q   = lane >> 3;
    const int l8  = lane & 7;
    const int a_moff = l8 + 8 * (q & 1);
    const int a_sadd = q >> 1;
    const int b_noff = l8 + 8 * (q >> 1);
    const int b_sadd = q & 1;

    float acc[2][8][4];
#pragma unroll
    for (int i = 0; i < 2; i++)
#pragma unroll
        for (int j = 0; j < 8; j++)
#pragma unroll
            for (int k = 0; k < 4; k++) acc[i][j][k] = 0.f;

    // loader mappings (512 threads)
    const int am   = tid >> 2;        // A row 0..127
    const int aslt = tid & 3;         // 16B slot 0..3
    const int bn   = tid >> 1;        // B row 0..255
    const int ls0  = (tid & 1) * 2;   // slots {ls0, ls0+1}
    const int arow = row0 + am;
    const bool apred = (arow < Mrows);

    const unsigned pa_off = am * 64 + 16 * (aslt ^ ((am >> 1) & 3));
    const unsigned b_off0 = bn * 64 + 16 * ((ls0 + 0) ^ ((bn >> 1) & 3));
    const unsigned b_off1 = bn * 64 + 16 * ((ls0 + 1) ^ ((bn >> 1) & 3));

    // ================= Phase 1: K = K1 (272) =================
    {
        const int nCh = K1 >> 4;    // 17
        float4 av, bv[2];
        // ---- load + store chunk 0, one sync ----
        {
            float4 v = make_float4(0.f, 0.f, 0.f, 0.f);
            if (apred) {
                const int k = aslt * 4;
                v = (k < DDIM) ? *(const float4*)(Ah + (long long)arow * DDIM + k)
                               : *(const float4*)(Asf + (long long)arow * 16 + (k - DDIM));
            }
            v.x = to_tf32(v.x); v.y = to_tf32(v.y);
            v.z = to_tf32(v.z); v.w = to_tf32(v.w);
            *(float4*)(smem + OFF_PA + pa_off) = v;
            bv[0] = *(const float4*)(Wt1 + (long long)bn * K1 + (ls0 + 0) * 4);
            bv[1] = *(const float4*)(Wt1 + (long long)bn * K1 + (ls0 + 1) * 4);
            *(float4*)(smem + OFF_B + b_off0) = bv[0];
            *(float4*)(smem + OFF_B + b_off1) = bv[1];
        }
        __syncthreads();

        int buf = 0;
        for (int t = 0; t < nCh; ++t) {
            const bool more = (t + 1 < nCh);
            // ---- prefetch chunk t+1 into regs ----
            if (more) {
                const int k0 = (t + 1) << 4;
                float4 v = make_float4(0.f, 0.f, 0.f, 0.f);
                if (apred) {
                    const int k = k0 + aslt * 4;
                    v = (k < DDIM) ? *(const float4*)(Ah + (long long)arow * DDIM + k)
                                   : *(const float4*)(Asf + (long long)arow * 16 + (k - DDIM));
                }
                av = v;
                bv[0] = *(const float4*)(Wt1 + (long long)bn * K1 + k0 + (ls0 + 0) * 4);
                bv[1] = *(const float4*)(Wt1 + (long long)bn * K1 + k0 + (ls0 + 1) * 4);
            }
            // ---- compute on buf ----
            const uint32_t Ab = sbase + OFF_PA + buf * 8192;
            const uint32_t Bb = sbase + OFF_B + buf * 16384;
#pragma unroll
            for (int ks = 0; ks < 2; ks++) {
                unsigned a[2][4];
#pragma unroll
                for (int mt = 0; mt < 2; mt++) {
                    const int m = wm * 32 + mt * 16 + a_moff;
                    const unsigned addr =
                        Ab + m * 64 + 16 * ((2 * ks + a_sadd) ^ ((a_moff >> 1) & 3));
                    ldsm4(a[mt][0], a[mt][1], a[mt][2], a[mt][3], addr);
                }
#pragma unroll
                for (int ntp = 0; ntp < 4; ntp++) {
                    const int n = wn * 64 + ntp * 16 + b_noff;
                    const unsigned addr =
                        Bb + n * 64 + 16 * ((2 * ks + b_sadd) ^ ((b_noff >> 1) & 3));
                    unsigned b0, b1x, b2x, b3;
                    ldsm4(b0, b1x, b2x, b3, addr);
                    mma_tf32(acc[0][2 * ntp], a[0], b0, b1x);
                    mma_tf32(acc[1][2 * ntp], a[1], b0, b1x);
                    mma_tf32(acc[0][2 * ntp + 1], a[0], b2x, b3);
                    mma_tf32(acc[1][2 * ntp + 1], a[1], b2x, b3);
                }
            }
            // ---- store prefetched into buf^1, single sync ----
            if (more) {
                float4 v = av;
                v.x = to_tf32(v.x); v.y = to_tf32(v.y);
                v.z = to_tf32(v.z); v.w = to_tf32(v.w);
                *(float4*)(smem + OFF_PA + (buf ^ 1) * 8192 + pa_off) = v;
                *(float4*)(smem + OFF_B + (buf ^ 1) * 16384 + b_off0) = bv[0];
                *(float4*)(smem + OFF_B + (buf ^ 1) * 16384 + b_off1) = bv[1];
                __syncthreads();
            }
            buf ^= 1;
        }
    }

    // ---- phase-1 epilogue: gelu+bias, tf32-round, write panels ----
#pragma unroll
    for (int nt = 0; nt < 8; nt++) {
        const int c = wn * 64 + nt * 8 + tig * 2;
        const float bv0 = b1[c];
        const float bv1 = b1[c + 1];
        char* pan = smem + OFF_PAN + (c >> 4) * 8192;
        const int s = (c >> 2) & 3;
        const int o = (c & 3) * 4;
#pragma unroll
        for (int mt = 0; mt < 2; mt++) {
            const int m1 = wm * 32 + mt * 16 + g;
            float2 o1;
            o1.x = to_tf32(gelu_f(acc[mt][nt][0] + bv0));
            o1.y = to_tf32(gelu_f(acc[mt][nt][1] + bv1));
            *(float2*)(pan + m1 * 64 + 16 * (s ^ ((m1 >> 1) & 3)) + o) = o1;
            const int m2 = m1 + 8;
            float2 o2;
            o2.x = to_tf32(gelu_f(acc[mt][nt][2] + bv0));
            o2.y = to_tf32(gelu_f(acc[mt][nt][3] + bv1));
            *(float2*)(pan + m2 * 64 + 16 * (s ^ ((m2 >> 1) & 3)) + o) = o2;
        }
    }
    __syncthreads();   // panels complete; B buffers free

    // ================= Phase 2: C2 = Y1 @ Wt2^T, K = 256 =================
#pragma unroll
    for (int i = 0; i < 2; i++)
#pragma unroll
        for (int j = 0; j < 8; j++)
#pragma unroll
            for (int k = 0; k < 4; k++) acc[i][j][k] = 0.f;
    {
        const int nCh = DDIM >> 4;  // 16
        float4 bv[2];
        {
            bv[0] = *(const float4*)(Wt2 + (long long)bn * DDIM + (ls0 + 0) * 4);
            bv[1] = *(const float4*)(Wt2 + (long long)bn * DDIM + (ls0 + 1) * 4);
            *(float4*)(smem + OFF_B + b_off0) = bv[0];
            *(float4*)(smem + OFF_B + b_off1) = bv[1];
        }
        __syncthreads();

        int buf = 0;
        for (int t = 0; t < nCh; ++t) {
            const bool more = (t + 1 < nCh);
            if (more) {
                const int k0 = (t + 1) << 4;
                bv[0] = *(const float4*)(Wt2 + (long long)bn * DDIM + k0 + (ls0 + 0) * 4);
                bv[1] = *(const float4*)(Wt2 + (long long)bn * DDIM + k0 + (ls0 + 1) * 4);
            }
            const uint32_t Ab = sbase + OFF_PAN + t * 8192;   // panel t
            const uint32_t Bb = sbase + OFF_B + buf * 16384;
#pragma unroll
            for (int ks = 0; ks < 2; ks++) {
                unsigned a[2][4];
#pragma unroll
                for (int mt = 0; mt < 2; mt++) {
                    const int m = wm * 32 + mt * 16 + a_moff;
                    const unsigned addr =
                        Ab + m * 64 + 16 * ((2 * ks + a_sadd) ^ ((a_moff >> 1) & 3));
                    ldsm4(a[mt][0], a[mt][1], a[mt][2], a[mt][3], addr);
                }
#pragma unroll
                for (int ntp = 0; ntp < 4; ntp++) {
                    const int n = wn * 64 + ntp * 16 + b_noff;
                    const unsigned addr =
                        Bb + n * 64 + 16 * ((2 * ks + b_sadd) ^ ((b_noff >> 1) & 3));
                    unsigned b0, b1x, b2x, b3;
                    ldsm4(b0, b1x, b2x, b3, addr);
                    mma_tf32(acc[0][2 * ntp], a[0], b0, b1x);
                    mma_tf32(acc[1][2 * ntp], a[1], b0, b1x);
                    mma_tf32(acc[0][2 * ntp + 1], a[0], b2x, b3);
                    mma_tf32(acc[1][2 * ntp + 1], a[1], b2x, b3);
                }
            }
            if (more) {
                *(float4*)(smem + OFF_B + (buf ^ 1) * 16384 + b_off0) = bv[0];
                *(float4*)(smem + OFF_B + (buf ^ 1) * 16384 + b_off1) = bv[1];
                __syncthreads();
            }
            buf ^= 1;
        }
    }

    // ---- epilogue: stage C2, run-length segment-sum ----
    __syncthreads();   // all panel reads done before overlay
#pragma unroll
    for (int nt = 0; nt < 8; nt++) {
        const int c = wn * 64 + nt * 8 + tig * 2;
#pragma unroll
        for (int mt = 0; mt < 2; mt++) {
            const int r1 = wm * 32 + mt * 16 + g;
            sbuf[r1 * 257 + c]           = acc[mt][nt][0];
            sbuf[r1 * 257 + c + 1]       = acc[mt][nt][1];
            sbuf[(r1 + 8) * 257 + c]     = acc[mt][nt][2];
            sbuf[(r1 + 8) * 257 + c + 1] = acc[mt][nt][3];
        }
    }
    if (tid < 128) {
        const int r = row0 + tid;
        sseg[tid] = (r < Mrows) ? seg[r] : -1;
    }
    __syncthreads();
    {
        const int c = tid & 255;
        const int rbeg = (tid >> 8) * 64;
        const float bb = b2[c];
        int cur = -1;
        float run = 0.f;
        for (int r = rbeg; r < rbeg + 64; r++) {
            const int s = sseg[r];
            if (s < 0) break;
            const float v = sbuf[r * 257 + c] + bb;
            if (s != cur) {
                if (cur >= 0) atomicAdd(&g_sums[(long long)cur * DDIM + c], run);
                cur = s;
                run = v;
            } else {
                run += v;
            }
        }
        if (cur >= 0) atomicAdd(&g_sums[(long long)cur * DDIM + c], run);
    }
}

// ===========================================================================
// GEMM3: g_T = gelu((g_sums*inv) @ Wt3^T + bc1), single-sync double buffer
// ===========================================================================
__global__ __launch_bounds__(256, 2) void gemm3_tc(
    const float* __restrict__ Wt, const float* __restrict__ bias, int Mrows)
{
    __shared__ float4 As4[2][512];
    __shared__ float4 Bs4[2][512];

    const int tid  = threadIdx.x;
    const int lane = tid & 31;
    const int warp = tid >> 5;
    const int wm   = warp >> 1;
    const int wn   = warp & 1;
    const int row0 = blockIdx.y * 128;
    const int col0 = blockIdx.x * 128;

    const unsigned Abase = (unsigned)__cvta_generic_to_shared(&As4[0][0]);
    const unsigned Bbase = (unsigned)__cvta_generic_to_shared(&Bs4[0][0]);

    float acc[2][8][4];
#pragma unroll
    for (int i = 0; i < 2; i++)
#pragma unroll
        for (int j = 0; j < 8; j++)
#pragma unroll
            for (int k = 0; k < 4; k++) acc[i][j][k] = 0.f;

    const int am   = tid >> 2;
    const int aslt = tid & 3;
    const int bn   = tid >> 1;
    const int bs0  = (tid & 1) * 2;

    const int q  = lane >> 3;
    const int l8 = lane & 7;
    const int a_moff = l8 + 8 * (q & 1);
    const int a_sadd = q >> 1;
    const int b_noff = l8 + 8 * (q >> 1);
    const int b_sadd = q & 1;

    const int nChunks = DDIM >> 4;

    float4 av[2], bv[2];
    // ---- load + store chunk 0 ----
    {
#pragma unroll
        for (int h2 = 0; h2 < 2; h2++) {
            const int m = am + 64 * h2;
            const int arow = row0 + m;
            float4 v = make_float4(0.f, 0.f, 0.f, 0.f);
            if (arow < Mrows) {
                v = *(const float4*)(g_sums + (long long)arow * DDIM + aslt * 4);
                const float sc = g_inv[arow];
                v.x = to_tf32(v.x * sc); v.y = to_tf32(v.y * sc);
                v.z = to_tf32(v.z * sc); v.w = to_tf32(v.w * sc);
            }
            As4[0][(m * 64 + 16 * (aslt ^ ((m >> 1) & 3))) >> 4] = v;
        }
#pragma unroll
        for (int s = 0; s < 2; s++) {
            const int slot = bs0 + s;
            Bs4[0][(bn * 64 + 16 * (slot ^ ((bn >> 1) & 3))) >> 4] =
                *(const float4*)(Wt + (long long)(col0 + bn) * DDIM + slot * 4);
        }
    }
    __syncthreads();

    int buf = 0;
    for (int t = 0; t < nChunks; ++t) {
        const bool more = (t + 1 < nChunks);
        if (more) {
            const int k0 = (t + 1) << 4;
#pragma unroll
            for (int h2 = 0; h2 < 2; h2++) {
                const int m = am + 64 * h2;
                const int arow = row0 + m;
                float4 v = make_float4(0.f, 0.f, 0.f, 0.f);
                if (arow < Mrows) {
                    v = *(const float4*)(g_sums + (long long)arow * DDIM + k0 + aslt * 4);
                    const float sc = g_inv[arow];
                    v.x *= sc; v.y *= sc; v.z *= sc; v.w *= sc;
                }
                av[h2] = v;
            }
#pragma unroll
            for (int s = 0; s < 2; s++)
                bv[s] = *(const float4*)(Wt + (long long)(col0 + bn) * DDIM + k0 + (bs0 + s) * 4);
        }

        const unsigned Ab = Abase + buf * 8192;
        const unsigned Bb = Bbase + buf * 8192;
#pragma unroll
        for (int ks = 0; ks < 2; ks++) {
            unsigned a[2][4];
#pragma unroll
            for (int mt = 0; mt < 2; mt++) {
                const int m = wm * 32 + mt * 16 + a_moff;
                const unsigned addr = Ab + m * 64 + 16 * ((2 * ks + a_sadd) ^ ((a_moff >> 1) & 3));
                ldsm4(a[mt][0], a[mt][1], a[mt][2], a[mt][3], addr);
            }
#pragma unroll
            for (int ntp = 0; ntp < 4; ntp++) {
                const int n = wn * 64 + ntp * 16 + b_noff;
                const unsigned addr = Bb + n * 64 + 16 * ((2 * ks + b_sadd) ^ ((b_noff >> 1) & 3));
                unsigned b0, b1, b2, b3;
                ldsm4(b0, b1, b2, b3, addr);
                mma_tf32(acc[0][2 * ntp], a[0], b0, b1);
                mma_tf32(acc[1][2 * ntp], a[1], b0, b1);
                mma_tf32(acc[0][2 * ntp + 1], a[0], b2, b3);
                mma_tf32(acc[1][2 * ntp + 1], a[1], b2, b3);
            }
        }

        if (more) {
#pragma unroll
            for (int h2 = 0; h2 < 2; h2++) {
                const int m = am + 64 * h2;
                float4 v = av[h2];
                v.x = to_tf32(v.x); v.y = to_tf32(v.y);
                v.z = to_tf32(v.z); v.w = to_tf32(v.w);
                As4[buf ^ 1][(m * 64 + 16 * (aslt ^ ((m >> 1) & 3))) >> 4] = v;
            }
#pragma unroll
            for (int s = 0; s < 2; s++) {
                const int slot = bs0 + s;
                Bs4[buf ^ 1][(bn * 64 + 16 * (slot ^ ((bn >> 1) & 3))) >> 4] = bv[s];
            }
            __syncthreads();
        }
        buf ^= 1;
    }

    const int g   = lane >> 2;
    const int tig = lane & 3;
#pragma unroll
    for (int nt = 0; nt < 8; nt++) {
        const int c = col0 + wn * 64 + nt * 8 + tig * 2;
        const float bv0 = bias[c];
        const float bv1 = bias[c + 1];
#pragma unroll
        for (int mt = 0; mt < 2; mt++) {
            const int r1 = row0 + wm * 32 + mt * 16 + g;
            if (r1 < Mrows) {
                float2 o;
                o.x = gelu_f(acc[mt][nt][0] + bv0);
                o.y = gelu_f(acc[mt][nt][1] + bv1);
                *(float2*)(g_T + (long long)r1 * DDIM + c) = o;
            }
            const int r2 = r1 + 8;
            if (r2 < Mrows) {
                float2 o;
                o.x = gelu_f(acc[mt][nt][2] + bv0);
                o.y = gelu_f(acc[mt][nt][3] + bv1);
                *(float2*)(g_T + (long long)r2 * DDIM + c) = o;
            }
        }
    }
}

// ---------------------------------------------------------------------------
__global__ void prep_w(const float* __restrict__ W, float* __restrict__ Wt, int K) {
    const int idx = blockIdx.x * blockDim.x + threadIdx.x;
    if (idx < K * DDIM) {
        const int k = idx / DDIM, n = idx % DDIM;
        Wt[n * K + k] = to_tf32(W[idx]);
    }
}

__global__ void zero_kernel(int G) {
    const long long total = (long long)G * DDIM;
    const long long stride = (long long)gridDim.x * blockDim.x;
    for (long long i = (long long)blockIdx.x * blockDim.x + threadIdx.x; i < total; i += stride)
        g_sums[i] = 0.f;
    for (long long i = (long long)blockIdx.x * blockDim.x + threadIdx.x; i < G; i += stride)
        g_cnt[i] = 0.f;
}

__global__ void count_kernel(const int* __restrict__ seg, int N) {
    const int i = blockIdx.x * blockDim.x + threadIdx.x;
    if (i < N) atomicAdd(&g_cnt[seg[i]], 1.0f);
}

__global__ void inv_kernel(int G) {
    const int i = blockIdx.x * blockDim.x + threadIdx.x;
    if (i < G) g_inv[i] = 1.0f / fmaxf(g_cnt[i], 1.0f);
}

__global__ __launch_bounds__(128) void head_kernel(
    const float* __restrict__ Wc2, const float* __restrict__ bc2,
    float* __restrict__ out, int G)
{
    __shared__ float sW[DDIM * CDIM];
    __shared__ float sb[CDIM];
    const int tid = threadIdx.x;
    for (int i = tid; i < DDIM * CDIM; i += 128) sW[i] = Wc2[i];
    if (tid < CDIM) sb[tid] = bc2[tid];
    __syncthreads();

    const int warp = tid >> 5;
    const int lane = tid & 31;
    const int g = blockIdx.x * 4 + warp;
    if (g >= G) return;

    const float* t = g_T + (long long)g * DDIM;
    const float4 v0 = *(const float4*)(t + lane * 8);
    const float4 v1 = *(const float4*)(t + lane * 8 + 4);
    const float tv[8] = {v0.x, v0.y, v0.z, v0.w, v1.x, v1.y, v1.z, v1.w};

    float acc[CDIM];
#pragma unroll
    for (int c = 0; c < CDIM; c++) acc[c] = 0.f;
#pragma unroll
    for (int u = 0; u < 8; u++) {
        const float* w = &sW[(lane * 8 + u) * CDIM];
#pragma unroll
        for (int c = 0; c < CDIM; c++) acc[c] += tv[u] * w[c];
    }
#pragma unroll
    for (int off = 16; off > 0; off >>= 1)
#pragma unroll
        for (int c = 0; c < CDIM; c++) acc[c] += __shfl_down_sync(0xffffffffu, acc[c], off);

    if (lane == 0) {
#pragma unroll
        for (int c = 0; c < CDIM; c++) out[(long long)g * CDIM + c] = acc[c] + sb[c];
    }
}

// ---------------------------------------------------------------------------
extern "C" void kernel_launch(void* const* d_in, const int* in_sizes, int n_in,
                              void* d_out, int out_size)
{
    const float* h   = (const float*)d_in[0];
    const float* sf  = (const float*)d_in[1];
    const float* W1a = (const float*)d_in[2];
    const float* b1a = (const float*)d_in[3];
    const float* W2a = (const float*)d_in[4];
    const float* b2a = (const float*)d_in[5];
    const float* Wc1 = (const float*)d_in[6];
    const float* bc1 = (const float*)d_in[7];
    const float* Wc2 = (const float*)d_in[8];
    const float* bc2 = (const float*)d_in[9];
    const int* seg   = (const int*)d_in[10];
    float* out = (float*)d_out;

    const int D = in_sizes[3];
    const int N = in_sizes[0] / D;
    const int C = in_sizes[8] / D;
    const int G = out_size / C;
    const int K1 = D + in_sizes[1] / N;   // 272

    float* wt1; cudaGetSymbolAddress((void**)&wt1, g_Wt1);
    float* wt2; cudaGetSymbolAddress((void**)&wt2, g_Wt2);
    float* wt3; cudaGetSymbolAddress((void**)&wt3, g_Wt3);

    cudaFuncSetAttribute(fused12, cudaFuncAttributeMaxDynamicSharedMemorySize, SMEM_F);

    prep_w<<<(K1 * D + 255) / 256, 256>>>(W1a, wt1, K1);
    prep_w<<<(D * D + 255) / 256, 256>>>(W2a, wt2, D);
    prep_w<<<(D * D + 255) / 256, 256>>>(Wc1, wt3, D);
    zero_kernel<<<2048, 256>>>(G);
    count_kernel<<<(N + 255) / 256, 256>>>(seg, N);
    fused12<<<(N + 127) / 128, 512, SMEM_F>>>(h, sf, wt1, b1a, wt2, b2a, seg, N, K1);
    inv_kernel<<<(G + 255) / 256, 256>>>(G);
    gemm3_tc<<<dim3(2, (G + 127) / 128), 256>>>(wt3, bc1, G);
    head_kernel<<<(G + 3) / 4, 128>>>(Wc2, bc2, out, G);
}

// round 9
// speedup vs baseline: 1.7282x; 1.0482x over previous
#include <cuda_runtime.h>
#include <math.h>
#include <stdint.h>

#define DDIM 256
#define CDIM 10
#define MAXN 500000
#define MAXG 100000

__device__ float g_sums[(long long)MAXG * DDIM];
__device__ float g_cnt[MAXG];
__device__ float g_Wt1[DDIM * 272];   // Wt[n][k] tf32-rounded
__device__ float g_Wt2[DDIM * DDIM];
__device__ float g_Wt3[DDIM * DDIM];

__device__ __forceinline__ float gelu_f(float x) {
    return 0.5f * x * (1.0f + erff(x * 0.70710678118654752f));
}
__device__ __forceinline__ float to_tf32(float x) {
    float r;
    asm("cvt.rna.tf32.f32 %0, %1;" : "=f"(r) : "f"(x));
    return r;
}
__device__ __forceinline__ void mma_tf32(float c[4], const unsigned a[4],
                                         unsigned b0, unsigned b1) {
    asm volatile(
        "mma.sync.aligned.m16n8k8.row.col.f32.tf32.tf32.f32 "
        "{%0,%1,%2,%3},{%4,%5,%6,%7},{%8,%9},{%0,%1,%2,%3};"
        : "+f"(c[0]), "+f"(c[1]), "+f"(c[2]), "+f"(c[3])
        : "r"(a[0]), "r"(a[1]), "r"(a[2]), "r"(a[3]), "r"(b0), "r"(b1));
}
__device__ __forceinline__ void ldsm4(unsigned &d0, unsigned &d1, unsigned &d2,
                                      unsigned &d3, unsigned addr) {
    asm volatile("ldmatrix.sync.aligned.m8n8.x4.shared.b16 {%0,%1,%2,%3}, [%4];"
                 : "=r"(d0), "=r"(d1), "=r"(d2), "=r"(d3) : "r"(addr));
}
// packed f32x2 helpers
__device__ __forceinline__ unsigned long long pk_dup(float a) {
    unsigned long long r;
    asm("mov.b64 %0, {%1, %1};" : "=l"(r) : "f"(a));
    return r;
}
__device__ __forceinline__ unsigned long long pk2(float lo, float hi) {
    unsigned long long r;
    asm("mov.b64 %0, {%1, %2};" : "=l"(r) : "f"(lo), "f"(hi));
    return r;
}
__device__ __forceinline__ void upk2(unsigned long long v, float &lo, float &hi) {
    asm("mov.b64 {%0, %1}, %2;" : "=f"(lo), "=f"(hi) : "l"(v));
}
__device__ __forceinline__ void fma2p(unsigned long long &acc, unsigned long long a,
                                      unsigned long long b) {
    asm("fma.rn.f32x2 %0, %1, %2, %0;" : "+l"(acc) : "l"(a), "l"(b));
}

// ---- fused-128 smem layout (bytes) ----
#define OFF_PAN 0            // 16 panels x 8KB = 128KB (Y1 tile, ldmatrix layout)
#define OFF_B   131072       // 2 x 16KB B tiles
#define OFF_PA  163840       // 2 x 8KB phase-1 A tiles
#define OFF_SSEG 180224      // 128 ints
#define SMEM_F  180736

// ===========================================================================
// Fused GEMM1+GEMM2 per 128-row band, 512 threads (16 warps as 4x4).
// Epilogue: run-length segment-sum (+ segment counts from the c==0 column).
// ===========================================================================
__global__ __launch_bounds__(512, 1) void fused12(
    const float* __restrict__ Ah, const float* __restrict__ Asf,
    const float* __restrict__ Wt1, const float* __restrict__ b1,
    const float* __restrict__ Wt2, const float* __restrict__ b2,
    const int* __restrict__ seg, int Mrows, int K1)
{
    extern __shared__ char smem[];
    const uint32_t sbase = (uint32_t)__cvta_generic_to_shared(smem);
    float* sbuf = (float*)smem;
    int* sseg = (int*)(smem + OFF_SSEG);

    const int tid  = threadIdx.x;
    const int lane = tid & 31;
    const int warp = tid >> 5;
    const int wm   = warp >> 2;
    const int wn   = warp & 3;
    const int row0 = blockIdx.x * 128;

    const int g   = lane >> 2;
    const int tig = lane & 3;
    const int q   = lane >> 3;
    const int l8  = lane & 7;
    const int a_moff = l8 + 8 * (q & 1);
    const int a_sadd = q >> 1;
    const int b_noff = l8 + 8 * (q >> 1);
    const int b_sadd = q & 1;

    float acc[2][8][4];
#pragma unroll
    for (int i = 0; i < 2; i++)
#pragma unroll
        for (int j = 0; j < 8; j++)
#pragma unroll
            for (int k = 0; k < 4; k++) acc[i][j][k] = 0.f;

    const int am   = tid >> 2;
    const int aslt = tid & 3;
    const int bn   = tid >> 1;
    const int ls0  = (tid & 1) * 2;
    const int arow = row0 + am;
    const bool apred = (arow < Mrows);

    const unsigned pa_off = am * 64 + 16 * (aslt ^ ((am >> 1) & 3));
    const unsigned b_off0 = bn * 64 + 16 * ((ls0 + 0) ^ ((bn >> 1) & 3));
    const unsigned b_off1 = bn * 64 + 16 * ((ls0 + 1) ^ ((bn >> 1) & 3));

    // ================= Phase 1: K = K1 (272) =================
    {
        const int nCh = K1 >> 4;    // 17
        float4 av, bv[2];
        {
            float4 v = make_float4(0.f, 0.f, 0.f, 0.f);
            if (apred) {
                const int k = aslt * 4;
                v = (k < DDIM) ? *(const float4*)(Ah + (long long)arow * DDIM + k)
                               : *(const float4*)(Asf + (long long)arow * 16 + (k - DDIM));
            }
            v.x = to_tf32(v.x); v.y = to_tf32(v.y);
            v.z = to_tf32(v.z); v.w = to_tf32(v.w);
            *(float4*)(smem + OFF_PA + pa_off) = v;
            bv[0] = *(const float4*)(Wt1 + (long long)bn * K1 + (ls0 + 0) * 4);
            bv[1] = *(const float4*)(Wt1 + (long long)bn * K1 + (ls0 + 1) * 4);
            *(float4*)(smem + OFF_B + b_off0) = bv[0];
            *(float4*)(smem + OFF_B + b_off1) = bv[1];
        }
        __syncthreads();

        int buf = 0;
        for (int t = 0; t < nCh; ++t) {
            const bool more = (t + 1 < nCh);
            if (more) {
                const int k0 = (t + 1) << 4;
                float4 v = make_float4(0.f, 0.f, 0.f, 0.f);
                if (apred) {
                    const int k = k0 + aslt * 4;
                    v = (k < DDIM) ? *(const float4*)(Ah + (long long)arow * DDIM + k)
                                   : *(const float4*)(Asf + (long long)arow * 16 + (k - DDIM));
                }
                av = v;
                bv[0] = *(const float4*)(Wt1 + (long long)bn * K1 + k0 + (ls0 + 0) * 4);
                bv[1] = *(const float4*)(Wt1 + (long long)bn * K1 + k0 + (ls0 + 1) * 4);
            }
            const uint32_t Ab = sbase + OFF_PA + buf * 8192;
            const uint32_t Bb = sbase + OFF_B + buf * 16384;
#pragma unroll
            for (int ks = 0; ks < 2; ks++) {
                unsigned a[2][4];
#pragma unroll
                for (int mt = 0; mt < 2; mt++) {
                    const int m = wm * 32 + mt * 16 + a_moff;
                    const unsigned addr =
                        Ab + m * 64 + 16 * ((2 * ks + a_sadd) ^ ((a_moff >> 1) & 3));
                    ldsm4(a[mt][0], a[mt][1], a[mt][2], a[mt][3], addr);
                }
#pragma unroll
                for (int ntp = 0; ntp < 4; ntp++) {
                    const int n = wn * 64 + ntp * 16 + b_noff;
                    const unsigned addr =
                        Bb + n * 64 + 16 * ((2 * ks + b_sadd) ^ ((b_noff >> 1) & 3));
                    unsigned b0, b1x, b2x, b3;
                    ldsm4(b0, b1x, b2x, b3, addr);
                    mma_tf32(acc[0][2 * ntp], a[0], b0, b1x);
                    mma_tf32(acc[1][2 * ntp], a[1], b0, b1x);
                    mma_tf32(acc[0][2 * ntp + 1], a[0], b2x, b3);
                    mma_tf32(acc[1][2 * ntp + 1], a[1], b2x, b3);
                }
            }
            if (more) {
                float4 v = av;
                v.x = to_tf32(v.x); v.y = to_tf32(v.y);
                v.z = to_tf32(v.z); v.w = to_tf32(v.w);
                *(float4*)(smem + OFF_PA + (buf ^ 1) * 8192 + pa_off) = v;
                *(float4*)(smem + OFF_B + (buf ^ 1) * 16384 + b_off0) = bv[0];
                *(float4*)(smem + OFF_B + (buf ^ 1) * 16384 + b_off1) = bv[1];
                __syncthreads();
            }
            buf ^= 1;
        }
    }

    // ---- phase-1 epilogue: gelu+bias, tf32-round, write panels ----
#pragma unroll
    for (int nt = 0; nt < 8; nt++) {
        const int c = wn * 64 + nt * 8 + tig * 2;
        const float bv0 = b1[c];
        const float bv1 = b1[c + 1];
        char* pan = smem + OFF_PAN + (c >> 4) * 8192;
        const int s = (c >> 2) & 3;
        const int o = (c & 3) * 4;
#pragma unroll
        for (int mt = 0; mt < 2; mt++) {
            const int m1 = wm * 32 + mt * 16 + g;
            float2 o1;
            o1.x = to_tf32(gelu_f(acc[mt][nt][0] + bv0));
            o1.y = to_tf32(gelu_f(acc[mt][nt][1] + bv1));
            *(float2*)(pan + m1 * 64 + 16 * (s ^ ((m1 >> 1) & 3)) + o) = o1;
            const int m2 = m1 + 8;
            float2 o2;
            o2.x = to_tf32(gelu_f(acc[mt][nt][2] + bv0));
            o2.y = to_tf32(gelu_f(acc[mt][nt][3] + bv1));
            *(float2*)(pan + m2 * 64 + 16 * (s ^ ((m2 >> 1) & 3)) + o) = o2;
        }
    }
    __syncthreads();

    // ================= Phase 2: C2 = Y1 @ Wt2^T, K = 256 =================
#pragma unroll
    for (int i = 0; i < 2; i++)
#pragma unroll
        for (int j = 0; j < 8; j++)
#pragma unroll
            for (int k = 0; k < 4; k++) acc[i][j][k] = 0.f;
    {
        const int nCh = DDIM >> 4;  // 16
        float4 bv[2];
        {
            bv[0] = *(const float4*)(Wt2 + (long long)bn * DDIM + (ls0 + 0) * 4);
            bv[1] = *(const float4*)(Wt2 + (long long)bn * DDIM + (ls0 + 1) * 4);
            *(float4*)(smem + OFF_B + b_off0) = bv[0];
            *(float4*)(smem + OFF_B + b_off1) = bv[1];
        }
        __syncthreads();

        int buf = 0;
        for (int t = 0; t < nCh; ++t) {
            const bool more = (t + 1 < nCh);
            if (more) {
                const int k0 = (t + 1) << 4;
                bv[0] = *(const float4*)(Wt2 + (long long)bn * DDIM + k0 + (ls0 + 0) * 4);
                bv[1] = *(const float4*)(Wt2 + (long long)bn * DDIM + k0 + (ls0 + 1) * 4);
            }
            const uint32_t Ab = sbase + OFF_PAN + t * 8192;
            const uint32_t Bb = sbase + OFF_B + buf * 16384;
#pragma unroll
            for (int ks = 0; ks < 2; ks++) {
                unsigned a[2][4];
#pragma unroll
                for (int mt = 0; mt < 2; mt++) {
                    const int m = wm * 32 + mt * 16 + a_moff;
                    const unsigned addr =
                        Ab + m * 64 + 16 * ((2 * ks + a_sadd) ^ ((a_moff >> 1) & 3));
                    ldsm4(a[mt][0], a[mt][1], a[mt][2], a[mt][3], addr);
                }
#pragma unroll
                for (int ntp = 0; ntp < 4; ntp++) {
                    const int n = wn * 64 + ntp * 16 + b_noff;
                    const unsigned addr =
                        Bb + n * 64 + 16 * ((2 * ks + b_sadd) ^ ((b_noff >> 1) & 3));
                    unsigned b0, b1x, b2x, b3;
                    ldsm4(b0, b1x, b2x, b3, addr);
                    mma_tf32(acc[0][2 * ntp], a[0], b0, b1x);
                    mma_tf32(acc[1][2 * ntp], a[1], b0, b1x);
                    mma_tf32(acc[0][2 * ntp + 1], a[0], b2x, b3);
                    mma_tf32(acc[1][2 * ntp + 1], a[1], b2x, b3);
                }
            }
            if (more) {
                *(float4*)(smem + OFF_B + (buf ^ 1) * 16384 + b_off0) = bv[0];
                *(float4*)(smem + OFF_B + (buf ^ 1) * 16384 + b_off1) = bv[1];
                __syncthreads();
            }
            buf ^= 1;
        }
    }

    // ---- epilogue: stage C2, run-length segment-sum + counts ----
    __syncthreads();
#pragma unroll
    for (int nt = 0; nt < 8; nt++) {
        const int c = wn * 64 + nt * 8 + tig * 2;
#pragma unroll
        for (int mt = 0; mt < 2; mt++) {
            const int r1 = wm * 32 + mt * 16 + g;
            sbuf[r1 * 257 + c]           = acc[mt][nt][0];
            sbuf[r1 * 257 + c + 1]       = acc[mt][nt][1];
            sbuf[(r1 + 8) * 257 + c]     = acc[mt][nt][2];
            sbuf[(r1 + 8) * 257 + c + 1] = acc[mt][nt][3];
        }
    }
    if (tid < 128) {
        const int r = row0 + tid;
        sseg[tid] = (r < Mrows) ? seg[r] : -1;
    }
    __syncthreads();
    {
        const int c = tid & 255;
        const int rbeg = (tid >> 8) * 64;
        const float bb = b2[c];
        int cur = -1;
        float run = 0.f;
        float rcnt = 0.f;
        for (int r = rbeg; r < rbeg + 64; r++) {
            const int s = sseg[r];
            if (s < 0) break;
            const float v = sbuf[r * 257 + c] + bb;
            if (s != cur) {
                if (cur >= 0) {
                    atomicAdd(&g_sums[(long long)cur * DDIM + c], run);
                    if (c == 0) atomicAdd(&g_cnt[cur], rcnt);
                }
                cur = s;
                run = v;
                rcnt = 1.f;
            } else {
                run += v;
                rcnt += 1.f;
            }
        }
        if (cur >= 0) {
            atomicAdd(&g_sums[(long long)cur * DDIM + c], run);
            if (c == 0) atomicAdd(&g_cnt[cur], rcnt);
        }
    }
}

// ===========================================================================
// GEMM3 + fused head:
//   T = gelu((g_sums/cnt) @ Wt3^T + bc1)   (in registers)
//   out += T-tile @ Wc2(col-block) [+ bc2 from the unique col0==0/wn==0 path]
// ===========================================================================
__global__ __launch_bounds__(256, 2) void gemm3_head(
    const float* __restrict__ Wt, const float* __restrict__ bias,
    const float* __restrict__ Wc2, const float* __restrict__ bc2,
    float* __restrict__ out, int Mrows)
{
    __shared__ float4 As4[2][512];
    __shared__ float4 Bs4[2][512];
    __shared__ float sWc[128 * CDIM];   // Wc2 rows for this col-block

    const int tid  = threadIdx.x;
    const int lane = tid & 31;
    const int warp = tid >> 5;
    const int wm   = warp >> 1;
    const int wn   = warp & 1;
    const int row0 = blockIdx.y * 128;
    const int col0 = blockIdx.x * 128;

    // load Wc2 col-block: sWc[i] = Wc2[col0*CDIM + i]
    for (int i = tid; i < 128 * CDIM; i += 256) sWc[i] = Wc2[col0 * CDIM + i];

    const unsigned Abase = (unsigned)__cvta_generic_to_shared(&As4[0][0]);
    const unsigned Bbase = (unsigned)__cvta_generic_to_shared(&Bs4[0][0]);

    float acc[2][8][4];
#pragma unroll
    for (int i = 0; i < 2; i++)
#pragma unroll
        for (int j = 0; j < 8; j++)
#pragma unroll
            for (int k = 0; k < 4; k++) acc[i][j][k] = 0.f;

    const int am   = tid >> 2;
    const int aslt = tid & 3;
    const int bn   = tid >> 1;
    const int bs0  = (tid & 1) * 2;

    const int q  = lane >> 3;
    const int l8 = lane & 7;
    const int a_moff = l8 + 8 * (q & 1);
    const int a_sadd = q >> 1;
    const int b_noff = l8 + 8 * (q >> 1);
    const int b_sadd = q & 1;

    const int nChunks = DDIM >> 4;

    float4 av[2], bv[2];
    {
#pragma unroll
        for (int h2 = 0; h2 < 2; h2++) {
            const int m = am + 64 * h2;
            const int arow = row0 + m;
            float4 v = make_float4(0.f, 0.f, 0.f, 0.f);
            if (arow < Mrows) {
                v = *(const float4*)(g_sums + (long long)arow * DDIM + aslt * 4);
                const float sc = 1.0f / fmaxf(g_cnt[arow], 1.0f);
                v.x = to_tf32(v.x * sc); v.y = to_tf32(v.y * sc);
                v.z = to_tf32(v.z * sc); v.w = to_tf32(v.w * sc);
            }
            As4[0][(m * 64 + 16 * (aslt ^ ((m >> 1) & 3))) >> 4] = v;
        }
#pragma unroll
        for (int s = 0; s < 2; s++) {
            const int slot = bs0 + s;
            Bs4[0][(bn * 64 + 16 * (slot ^ ((bn >> 1) & 3))) >> 4] =
                *(const float4*)(Wt + (long long)(col0 + bn) * DDIM + slot * 4);
        }
    }
    __syncthreads();

    int buf = 0;
    for (int t = 0; t < nChunks; ++t) {
        const bool more = (t + 1 < nChunks);
        if (more) {
            const int k0 = (t + 1) << 4;
#pragma unroll
            for (int h2 = 0; h2 < 2; h2++) {
                const int m = am + 64 * h2;
                const int arow = row0 + m;
                float4 v = make_float4(0.f, 0.f, 0.f, 0.f);
                if (arow < Mrows) {
                    v = *(const float4*)(g_sums + (long long)arow * DDIM + k0 + aslt * 4);
                    const float sc = 1.0f / fmaxf(g_cnt[arow], 1.0f);
                    v.x *= sc; v.y *= sc; v.z *= sc; v.w *= sc;
                }
                av[h2] = v;
            }
#pragma unroll
            for (int s = 0; s < 2; s++)
                bv[s] = *(const float4*)(Wt + (long long)(col0 + bn) * DDIM + k0 + (bs0 + s) * 4);
        }

        const unsigned Ab = Abase + buf * 8192;
        const unsigned Bb = Bbase + buf * 8192;
#pragma unroll
        for (int ks = 0; ks < 2; ks++) {
            unsigned a[2][4];
#pragma unroll
            for (int mt = 0; mt < 2; mt++) {
                const int m = wm * 32 + mt * 16 + a_moff;
                const unsigned addr = Ab + m * 64 + 16 * ((2 * ks + a_sadd) ^ ((a_moff >> 1) & 3));
                ldsm4(a[mt][0], a[mt][1], a[mt][2], a[mt][3], addr);
            }
#pragma unroll
            for (int ntp = 0; ntp < 4; ntp++) {
                const int n = wn * 64 + ntp * 16 + b_noff;
                const unsigned addr = Bb + n * 64 + 16 * ((2 * ks + b_sadd) ^ ((b_noff >> 1) & 3));
                unsigned b0, b1, b2, b3;
                ldsm4(b0, b1, b2, b3, addr);
                mma_tf32(acc[0][2 * ntp], a[0], b0, b1);
                mma_tf32(acc[1][2 * ntp], a[1], b0, b1);
                mma_tf32(acc[0][2 * ntp + 1], a[0], b2, b3);
                mma_tf32(acc[1][2 * ntp + 1], a[1], b2, b3);
            }
        }

        if (more) {
#pragma unroll
            for (int h2 = 0; h2 < 2; h2++) {
                const int m = am + 64 * h2;
                float4 v = av[h2];
                v.x = to_tf32(v.x); v.y = to_tf32(v.y);
                v.z = to_tf32(v.z); v.w = to_tf32(v.w);
                As4[buf ^ 1][(m * 64 + 16 * (aslt ^ ((m >> 1) & 3))) >> 4] = v;
            }
#pragma unroll
            for (int s = 0; s < 2; s++) {
                const int slot = bs0 + s;
                Bs4[buf ^ 1][(bn * 64 + 16 * (slot ^ ((bn >> 1) & 3))) >> 4] = bv[s];
            }
            __syncthreads();
        }
        buf ^= 1;
    }

    // ---- fused head epilogue ----
    const int g   = lane >> 2;
    const int tig = lane & 3;
    float bvv[8][2];
#pragma unroll
    for (int nt = 0; nt < 8; nt++) {
        const int c = col0 + wn * 64 + nt * 8 + tig * 2;
        bvv[nt][0] = bias[c];
        bvv[nt][1] = bias[c + 1];
    }
    const bool addb = (col0 == 0) && (wn == 0);

#pragma unroll
    for (int mt = 0; mt < 2; mt++) {
#pragma unroll
        for (int half = 0; half < 2; half++) {
            const int r = row0 + wm * 32 + mt * 16 + g + half * 8;
            unsigned long long cls[5];
#pragma unroll
            for (int c5 = 0; c5 < 5; c5++) cls[c5] = 0ull;
#pragma unroll
            for (int nt = 0; nt < 8; nt++) {
                const int cl = wn * 64 + nt * 8 + tig * 2;   // local col
                const float v0 = gelu_f(acc[mt][nt][half * 2 + 0] + bvv[nt][0]);
                const float v1 = gelu_f(acc[mt][nt][half * 2 + 1] + bvv[nt][1]);
                const float2* w0 = (const float2*)&sWc[cl * CDIM];
                const float2* w1 = (const float2*)&sWc[(cl + 1) * CDIM];
                const unsigned long long p0 = pk_dup(v0);
                const unsigned long long p1 = pk_dup(v1);
#pragma unroll
                for (int c5 = 0; c5 < 5; c5++) {
                    const float2 a0 = w0[c5];
                    const float2 a1 = w1[c5];
                    fma2p(cls[c5], p0, pk2(a0.x, a0.y));
                    fma2p(cls[c5], p1, pk2(a1.x, a1.y));
                }
            }
            float cf[CDIM];
#pragma unroll
            for (int c5 = 0; c5 < 5; c5++) upk2(cls[c5], cf[2 * c5], cf[2 * c5 + 1]);
#pragma unroll
            for (int off = 1; off < 4; off <<= 1)
#pragma unroll
                for (int c = 0; c < CDIM; c++)
                    cf[c] += __shfl_xor_sync(0xffffffffu, cf[c], off);
            if (tig == 0 && r < Mrows) {
#pragma unroll
                for (int c = 0; c < CDIM; c++) {
                    const float add = addb ? bc2[c] : 0.f;
                    atomicAdd(&out[(long long)r * CDIM + c], cf[c] + add);
                }
            }
        }
    }
}

// ---------------------------------------------------------------------------
__global__ void prep_w(const float* __restrict__ W, float* __restrict__ Wt, int K) {
    const int idx = blockIdx.x * blockDim.x + threadIdx.x;
    if (idx < K * DDIM) {
        const int k = idx / DDIM, n = idx % DDIM;
        Wt[n * K + k] = to_tf32(W[idx]);
    }
}

__global__ void zero_kernel(float* __restrict__ out, int G) {
    const long long total = (long long)G * DDIM;
    const long long stride = (long long)gridDim.x * blockDim.x;
    const long long i0 = (long long)blockIdx.x * blockDim.x + threadIdx.x;
    for (long long i = i0; i < total; i += stride) g_sums[i] = 0.f;
    for (long long i = i0; i < G; i += stride) g_cnt[i] = 0.f;
    for (long long i = i0; i < (long long)G * CDIM; i += stride) out[i] = 0.f;
}

// ---------------------------------------------------------------------------
extern "C" void kernel_launch(void* const* d_in, const int* in_sizes, int n_in,
                              void* d_out, int out_size)
{
    const float* h   = (const float*)d_in[0];
    const float* sf  = (const float*)d_in[1];
    const float* W1a = (const float*)d_in[2];
    const float* b1a = (const float*)d_in[3];
    const float* W2a = (const float*)d_in[4];
    const float* b2a = (const float*)d_in[5];
    const float* Wc1 = (const float*)d_in[6];
    const float* bc1 = (const float*)d_in[7];
    const float* Wc2 = (const float*)d_in[8];
    const float* bc2 = (const float*)d_in[9];
    const int* seg   = (const int*)d_in[10];
    float* out = (float*)d_out;

    const int D = in_sizes[3];
    const int N = in_sizes[0] / D;
    const int C = in_sizes[8] / D;
    const int G = out_size / C;
    const int K1 = D + in_sizes[1] / N;   // 272

    float* wt1; cudaGetSymbolAddress((void**)&wt1, g_Wt1);
    float* wt2; cudaGetSymbolAddress((void**)&wt2, g_Wt2);
    float* wt3; cudaGetSymbolAddress((void**)&wt3, g_Wt3);

    cudaFuncSetAttribute(fused12, cudaFuncAttributeMaxDynamicSharedMemorySize, SMEM_F);

    prep_w<<<(K1 * D + 255) / 256, 256>>>(W1a, wt1, K1);
    prep_w<<<(D * D + 255) / 256, 256>>>(W2a, wt2, D);
    prep_w<<<(D * D + 255) / 256, 256>>>(Wc1, wt3, D);
    zero_kernel<<<2048, 256>>>(out, G);
    fused12<<<(N + 127) / 128, 512, SMEM_F>>>(h, sf, wt1, b1a, wt2, b2a, seg, N, K1);
    gemm3_head<<<dim3(2, (G + 127) / 128), 256>>>(wt3, bc1, Wc2, bc2, out, G);
}

// round 10
// speedup vs baseline: 2.3323x; 1.3495x over previous
#include <cuda_runtime.h>
#include <cuda_fp16.h>
#include <math.h>
#include <stdint.h>

#define DDIM 256
#define CDIM 10
#define MAXG 100000
#define K1PAD 288

__device__ float g_sums[(long long)MAXG * DDIM];
__device__ float g_cnt[MAXG];
__device__ __half g_Wt1h[DDIM * K1PAD];   // Wt[n][k] fp16, zero-padded K
__device__ __half g_Wt2h[DDIM * DDIM];
__device__ __half g_Wt3h[DDIM * DDIM];

__device__ __forceinline__ float gelu_f(float x) {
    return 0.5f * x * (1.0f + erff(x * 0.70710678118654752f));
}
__device__ __forceinline__ void mma_f16(float c[4], const unsigned a[4],
                                        unsigned b0, unsigned b1) {
    asm volatile(
        "mma.sync.aligned.m16n8k16.row.col.f32.f16.f16.f32 "
        "{%0,%1,%2,%3},{%4,%5,%6,%7},{%8,%9},{%0,%1,%2,%3};"
        : "+f"(c[0]), "+f"(c[1]), "+f"(c[2]), "+f"(c[3])
        : "r"(a[0]), "r"(a[1]), "r"(a[2]), "r"(a[3]), "r"(b0), "r"(b1));
}
__device__ __forceinline__ void ldsm4(unsigned &d0, unsigned &d1, unsigned &d2,
                                      unsigned &d3, unsigned addr) {
    asm volatile("ldmatrix.sync.aligned.m8n8.x4.shared.b16 {%0,%1,%2,%3}, [%4];"
                 : "=r"(d0), "=r"(d1), "=r"(d2), "=r"(d3) : "r"(addr));
}
__device__ __forceinline__ unsigned h2u(__half2 h) {
    return *reinterpret_cast<unsigned*>(&h);
}
__device__ __forceinline__ uint4 pack8(float4 v0, float4 v1) {
    uint4 u;
    u.x = h2u(__floats2half2_rn(v0.x, v0.y));
    u.y = h2u(__floats2half2_rn(v0.z, v0.w));
    u.z = h2u(__floats2half2_rn(v1.x, v1.y));
    u.w = h2u(__floats2half2_rn(v1.z, v1.w));
    return u;
}
// packed f32x2 helpers (head epilogue)
__device__ __forceinline__ unsigned long long pk_dup(float a) {
    unsigned long long r;
    asm("mov.b64 %0, {%1, %1};" : "=l"(r) : "f"(a));
    return r;
}
__device__ __forceinline__ unsigned long long pk2(float lo, float hi) {
    unsigned long long r;
    asm("mov.b64 %0, {%1, %2};" : "=l"(r) : "f"(lo), "f"(hi));
    return r;
}
__device__ __forceinline__ void upk2(unsigned long long v, float &lo, float &hi) {
    asm("mov.b64 {%0, %1}, %2;" : "=f"(lo), "=f"(hi) : "l"(v));
}
__device__ __forceinline__ void fma2p(unsigned long long &acc, unsigned long long a,
                                      unsigned long long b) {
    asm("fma.rn.f32x2 %0, %1, %2, %0;" : "+l"(acc) : "l"(a), "l"(b));
}

// ---- fused-128 smem layout (bytes) ----
#define OFF_PAN 0            // 8 panels x 8KB = 64KB (Y1 fp16, ldmatrix layout)
#define OFF_B   65536        // 2 x 16KB B tiles (256n x 32k fp16, swizzled)
#define OFF_PA  98304        // 2 x 8KB A tiles (128m x 32k fp16)
#define OFF_SSEG 131584      // after sbuf overlay (128*257*4 = 131584)
#define SMEM_F  132096

// A load helper (fused12 phase 1): 8 consecutive k-floats, fp16-packed
__device__ __forceinline__ uint4 load_a12(const float* __restrict__ Ah,
                                          const float* __restrict__ Asf,
                                          int arow, bool apred, int k0) {
    float4 v0 = make_float4(0.f, 0.f, 0.f, 0.f);
    float4 v1 = v0;
    if (apred) {
        if (k0 < DDIM) {
            v0 = *(const float4*)(Ah + (long long)arow * DDIM + k0);
            v1 = *(const float4*)(Ah + (long long)arow * DDIM + k0 + 4);
        } else if (k0 < 272) {
            v0 = *(const float4*)(Asf + (long long)arow * 16 + (k0 - DDIM));
            v1 = *(const float4*)(Asf + (long long)arow * 16 + (k0 - DDIM) + 4);
        }
    }
    return pack8(v0, v1);
}

// ===========================================================================
// Fused GEMM1+GEMM2 per 128-row band, 512 threads (16 warps as 4x4), fp16 MMA.
// BK=32 (two m16n8k16 steps per chunk). Phase1 9 chunks (K1pad=288),
// Phase2 8 chunks (K=256, A = Y1 panels in smem).
// ===========================================================================
__global__ __launch_bounds__(512, 1) void fused12(
    const float* __restrict__ Ah, const float* __restrict__ Asf,
    const __half* __restrict__ Wt1, const float* __restrict__ b1,
    const __half* __restrict__ Wt2, const float* __restrict__ b2,
    const int* __restrict__ seg, int Mrows)
{
    extern __shared__ char smem[];
    const uint32_t sbase = (uint32_t)__cvta_generic_to_shared(smem);
    float* sbuf = (float*)smem;
    int* sseg = (int*)(smem + OFF_SSEG);

    const int tid  = threadIdx.x;
    const int lane = tid & 31;
    const int warp = tid >> 5;
    const int wm   = warp >> 2;
    const int wn   = warp & 3;
    const int row0 = blockIdx.x * 128;

    const int g   = lane >> 2;
    const int tig = lane & 3;
    const int q   = lane >> 3;
    const int l8  = lane & 7;
    const int a_moff = l8 + 8 * (q & 1);
    const int a_sadd = q >> 1;
    const int b_noff = l8 + 8 * (q >> 1);
    const int b_sadd = q & 1;

    float acc[2][8][4];
#pragma unroll
    for (int i = 0; i < 2; i++)
#pragma unroll
        for (int j = 0; j < 8; j++)
#pragma unroll
            for (int k = 0; k < 4; k++) acc[i][j][k] = 0.f;

    // loader mappings (512 threads)
    const int am   = tid >> 2;        // A row 0..127
    const int aslt = tid & 3;         // 16B slot (k8 group) 0..3
    const int bn   = tid >> 1;        // B row 0..255
    const int bls  = (tid & 1) * 2;   // B slots {bls, bls+1}
    const int arow = row0 + am;
    const bool apred = (arow < Mrows);

    const unsigned pa_off = am * 64 + 16 * (aslt ^ ((am >> 1) & 3));
    const unsigned b_off0 = bn * 64 + 16 * ((bls + 0) ^ ((bn >> 1) & 3));
    const unsigned b_off1 = bn * 64 + 16 * ((bls + 1) ^ ((bn >> 1) & 3));

    // ================= Phase 1: 9 chunks of k32 =================
    {
        const int nCh = 9;
        uint4 au, bu[2];
        {   // chunk 0
            au = load_a12(Ah, Asf, arow, apred, aslt * 8);
            *(uint4*)(smem + OFF_PA + pa_off) = au;
            bu[0] = *(const uint4*)(Wt1 + (long long)bn * K1PAD + (bls + 0) * 8);
            bu[1] = *(const uint4*)(Wt1 + (long long)bn * K1PAD + (bls + 1) * 8);
            *(uint4*)(smem + OFF_B + b_off0) = bu[0];
            *(uint4*)(smem + OFF_B + b_off1) = bu[1];
        }
        __syncthreads();

        int buf = 0;
        for (int t = 0; t < nCh; ++t) {
            const bool more = (t + 1 < nCh);
            if (more) {
                const int k0 = (t + 1) << 5;
                au = load_a12(Ah, Asf, arow, apred, k0 + aslt * 8);
                bu[0] = *(const uint4*)(Wt1 + (long long)bn * K1PAD + k0 + (bls + 0) * 8);
                bu[1] = *(const uint4*)(Wt1 + (long long)bn * K1PAD + k0 + (bls + 1) * 8);
            }
            const uint32_t Ab = sbase + OFF_PA + buf * 8192;
            const uint32_t Bb = sbase + OFF_B + buf * 16384;
#pragma unroll
            for (int ks = 0; ks < 2; ks++) {
                unsigned a[2][4];
#pragma unroll
                for (int mt = 0; mt < 2; mt++) {
                    const int m = wm * 32 + mt * 16 + a_moff;
                    const unsigned addr =
                        Ab + m * 64 + 16 * ((2 * ks + a_sadd) ^ ((a_moff >> 1) & 3));
                    ldsm4(a[mt][0], a[mt][1], a[mt][2], a[mt][3], addr);
                }
#pragma unroll
                for (int ntp = 0; ntp < 4; ntp++) {
                    const int n = wn * 64 + ntp * 16 + b_noff;
                    const unsigned addr =
                        Bb + n * 64 + 16 * ((2 * ks + b_sadd) ^ ((b_noff >> 1) & 3));
                    unsigned b0, b1x, b2x, b3;
                    ldsm4(b0, b1x, b2x, b3, addr);
                    mma_f16(acc[0][2 * ntp], a[0], b0, b1x);
                    mma_f16(acc[1][2 * ntp], a[1], b0, b1x);
                    mma_f16(acc[0][2 * ntp + 1], a[0], b2x, b3);
                    mma_f16(acc[1][2 * ntp + 1], a[1], b2x, b3);
                }
            }
            if (more) {
                *(uint4*)(smem + OFF_PA + (buf ^ 1) * 8192 + pa_off) = au;
                *(uint4*)(smem + OFF_B + (buf ^ 1) * 16384 + b_off0) = bu[0];
                *(uint4*)(smem + OFF_B + (buf ^ 1) * 16384 + b_off1) = bu[1];
                __syncthreads();
            }
            buf ^= 1;
        }
    }

    // ---- phase-1 epilogue: gelu+bias -> fp16 Y1 panels ----
#pragma unroll
    for (int nt = 0; nt < 8; nt++) {
        const int c = wn * 64 + nt * 8 + tig * 2;
        const float bv0 = b1[c];
        const float bv1 = b1[c + 1];
        char* pan = smem + OFF_PAN + (c >> 5) * 8192;
        const int cin = c & 31;
        const int slot = cin >> 3;
        const int o = (cin & 7) * 2;
#pragma unroll
        for (int mt = 0; mt < 2; mt++) {
            const int m1 = wm * 32 + mt * 16 + g;
            *(__half2*)(pan + m1 * 64 + 16 * (slot ^ ((m1 >> 1) & 3)) + o) =
                __floats2half2_rn(gelu_f(acc[mt][nt][0] + bv0),
                                  gelu_f(acc[mt][nt][1] + bv1));
            const int m2 = m1 + 8;
            *(__half2*)(pan + m2 * 64 + 16 * (slot ^ ((m2 >> 1) & 3)) + o) =
                __floats2half2_rn(gelu_f(acc[mt][nt][2] + bv0),
                                  gelu_f(acc[mt][nt][3] + bv1));
        }
    }
    __syncthreads();   // panels complete; A/B buffers free

    // ================= Phase 2: C2 = Y1 @ Wt2^T, 8 chunks of k32 =================
#pragma unroll
    for (int i = 0; i < 2; i++)
#pragma unroll
        for (int j = 0; j < 8; j++)
#pragma unroll
            for (int k = 0; k < 4; k++) acc[i][j][k] = 0.f;
    {
        uint4 bu[2];
        {
            bu[0] = *(const uint4*)(Wt2 + (long long)bn * DDIM + (bls + 0) * 8);
            bu[1] = *(const uint4*)(Wt2 + (long long)bn * DDIM + (bls + 1) * 8);
            *(uint4*)(smem + OFF_B + b_off0) = bu[0];
            *(uint4*)(smem + OFF_B + b_off1) = bu[1];
        }
        __syncthreads();

        int buf = 0;
        for (int t = 0; t < 8; ++t) {
            const bool more = (t + 1 < 8);
            if (more) {
                const int k0 = (t + 1) << 5;
                bu[0] = *(const uint4*)(Wt2 + (long long)bn * DDIM + k0 + (bls + 0) * 8);
                bu[1] = *(const uint4*)(Wt2 + (long long)bn * DDIM + k0 + (bls + 1) * 8);
            }
            const uint32_t Ab = sbase + OFF_PAN + t * 8192;   // panel t
            const uint32_t Bb = sbase + OFF_B + buf * 16384;
#pragma unroll
            for (int ks = 0; ks < 2; ks++) {
                unsigned a[2][4];
#pragma unroll
                for (int mt = 0; mt < 2; mt++) {
                    const int m = wm * 32 + mt * 16 + a_moff;
                    const unsigned addr =
                        Ab + m * 64 + 16 * ((2 * ks + a_sadd) ^ ((a_moff >> 1) & 3));
                    ldsm4(a[mt][0], a[mt][1], a[mt][2], a[mt][3], addr);
                }
#pragma unroll
                for (int ntp = 0; ntp < 4; ntp++) {
                    const int n = wn * 64 + ntp * 16 + b_noff;
                    const unsigned addr =
                        Bb + n * 64 + 16 * ((2 * ks + b_sadd) ^ ((b_noff >> 1) & 3));
                    unsigned b0, b1x, b2x, b3;
                    ldsm4(b0, b1x, b2x, b3, addr);
                    mma_f16(acc[0][2 * ntp], a[0], b0, b1x);
                    mma_f16(acc[1][2 * ntp], a[1], b0, b1x);
                    mma_f16(acc[0][2 * ntp + 1], a[0], b2x, b3);
                    mma_f16(acc[1][2 * ntp + 1], a[1], b2x, b3);
                }
            }
            if (more) {
                *(uint4*)(smem + OFF_B + (buf ^ 1) * 16384 + b_off0) = bu[0];
                *(uint4*)(smem + OFF_B + (buf ^ 1) * 16384 + b_off1) = bu[1];
                __syncthreads();
            }
            buf ^= 1;
        }
    }

    // ---- epilogue: stage C2, run-length segment-sum + counts ----
    __syncthreads();
#pragma unroll
    for (int nt = 0; nt < 8; nt++) {
        const int c = wn * 64 + nt * 8 + tig * 2;
#pragma unroll
        for (int mt = 0; mt < 2; mt++) {
            const int r1 = wm * 32 + mt * 16 + g;
            sbuf[r1 * 257 + c]           = acc[mt][nt][0];
            sbuf[r1 * 257 + c + 1]       = acc[mt][nt][1];
            sbuf[(r1 + 8) * 257 + c]     = acc[mt][nt][2];
            sbuf[(r1 + 8) * 257 + c + 1] = acc[mt][nt][3];
        }
    }
    if (tid < 128) {
        const int r = row0 + tid;
        sseg[tid] = (r < Mrows) ? seg[r] : -1;
    }
    __syncthreads();
    {
        const int c = tid & 255;
        const int rbeg = (tid >> 8) * 64;
        const float bb = b2[c];
        int cur = -1;
        float run = 0.f;
        float rcnt = 0.f;
        for (int r = rbeg; r < rbeg + 64; r++) {
            const int s = sseg[r];
            if (s < 0) break;
            const float v = sbuf[r * 257 + c] + bb;
            if (s != cur) {
                if (cur >= 0) {
                    atomicAdd(&g_sums[(long long)cur * DDIM + c], run);
                    if (c == 0) atomicAdd(&g_cnt[cur], rcnt);
                }
                cur = s;
                run = v;
                rcnt = 1.f;
            } else {
                run += v;
                rcnt += 1.f;
            }
        }
        if (cur >= 0) {
            atomicAdd(&g_sums[(long long)cur * DDIM + c], run);
            if (c == 0) atomicAdd(&g_cnt[cur], rcnt);
        }
    }
}

// ===========================================================================
// GEMM3 + fused head (fp16 MMA, BK=32, 8 chunks):
//   T = gelu((g_sums/cnt) @ Wt3^T + bc1); out += T @ Wc2 (+ bc2 once)
// ===========================================================================
__global__ __launch_bounds__(256, 2) void gemm3_head(
    const __half* __restrict__ Wt, const float* __restrict__ bias,
    const float* __restrict__ Wc2, const float* __restrict__ bc2,
    float* __restrict__ out, int Mrows)
{
    __shared__ uint4 As4[2][512];
    __shared__ uint4 Bs4[2][512];
    __shared__ float sWc[128 * CDIM];

    const int tid  = threadIdx.x;
    const int lane = tid & 31;
    const int warp = tid >> 5;
    const int wm   = warp >> 1;
    const int wn   = warp & 1;
    const int row0 = blockIdx.y * 128;
    const int col0 = blockIdx.x * 128;

    for (int i = tid; i < 128 * CDIM; i += 256) sWc[i] = Wc2[col0 * CDIM + i];

    const unsigned Abase = (unsigned)__cvta_generic_to_shared(&As4[0][0]);
    const unsigned Bbase = (unsigned)__cvta_generic_to_shared(&Bs4[0][0]);

    float acc[2][8][4];
#pragma unroll
    for (int i = 0; i < 2; i++)
#pragma unroll
        for (int j = 0; j < 8; j++)
#pragma unroll
            for (int k = 0; k < 4; k++) acc[i][j][k] = 0.f;

    const int lrow = tid >> 1;        // 0..127 (A m-row; B n-row)
    const int bls  = (tid & 1) * 2;   // slots {bls, bls+1}
    const int arow = row0 + lrow;
    const bool apred = (arow < Mrows);
    const float sc = apred ? 1.0f / fmaxf(g_cnt[arow], 1.0f) : 0.f;

    const unsigned off0 = lrow * 64 + 16 * ((bls + 0) ^ ((lrow >> 1) & 3));
    const unsigned off1 = lrow * 64 + 16 * ((bls + 1) ^ ((lrow >> 1) & 3));

    const int q  = lane >> 3;
    const int l8 = lane & 7;
    const int a_moff = l8 + 8 * (q & 1);
    const int a_sadd = q >> 1;
    const int b_noff = l8 + 8 * (q >> 1);
    const int b_sadd = q & 1;

    uint4 au[2], bu[2];
    // chunk 0
    {
#pragma unroll
        for (int s = 0; s < 2; s++) {
            const int k = (bls + s) * 8;
            float4 v0 = make_float4(0.f, 0.f, 0.f, 0.f), v1 = v0;
            if (apred) {
                v0 = *(const float4*)(g_sums + (long long)arow * DDIM + k);
                v1 = *(const float4*)(g_sums + (long long)arow * DDIM + k + 4);
                v0.x *= sc; v0.y *= sc; v0.z *= sc; v0.w *= sc;
                v1.x *= sc; v1.y *= sc; v1.z *= sc; v1.w *= sc;
            }
            au[s] = pack8(v0, v1);
            bu[s] = *(const uint4*)(Wt + (long long)(col0 + lrow) * DDIM + k);
        }
        *(uint4*)((char*)&As4[0][0] + off0) = au[0];
        *(uint4*)((char*)&As4[0][0] + off1) = au[1];
        *(uint4*)((char*)&Bs4[0][0] + off0) = bu[0];
        *(uint4*)((char*)&Bs4[0][0] + off1) = bu[1];
    }
    __syncthreads();

    int buf = 0;
    for (int t = 0; t < 8; ++t) {
        const bool more = (t + 1 < 8);
        if (more) {
            const int k0 = (t + 1) << 5;
#pragma unroll
            for (int s = 0; s < 2; s++) {
                const int k = k0 + (bls + s) * 8;
                float4 v0 = make_float4(0.f, 0.f, 0.f, 0.f), v1 = v0;
                if (apred) {
                    v0 = *(const float4*)(g_sums + (long long)arow * DDIM + k);
                    v1 = *(const float4*)(g_sums + (long long)arow * DDIM + k + 4);
                    v0.x *= sc; v0.y *= sc; v0.z *= sc; v0.w *= sc;
                    v1.x *= sc; v1.y *= sc; v1.z *= sc; v1.w *= sc;
                }
                au[s] = pack8(v0, v1);
                bu[s] = *(const uint4*)(Wt + (long long)(col0 + lrow) * DDIM + k);
            }
        }

        const unsigned Ab = Abase + buf * 8192;
        const unsigned Bb = Bbase + buf * 8192;
#pragma unroll
        for (int ks = 0; ks < 2; ks++) {
            unsigned a[2][4];
#pragma unroll
            for (int mt = 0; mt < 2; mt++) {
                const int m = wm * 32 + mt * 16 + a_moff;
                const unsigned addr = Ab + m * 64 + 16 * ((2 * ks + a_sadd) ^ ((a_moff >> 1) & 3));
                ldsm4(a[mt][0], a[mt][1], a[mt][2], a[mt][3], addr);
            }
#pragma unroll
            for (int ntp = 0; ntp < 4; ntp++) {
                const int n = wn * 64 + ntp * 16 + b_noff;
                const unsigned addr = Bb + n * 64 + 16 * ((2 * ks + b_sadd) ^ ((b_noff >> 1) & 3));
                unsigned b0, b1, b2, b3;
                ldsm4(b0, b1, b2, b3, addr);
                mma_f16(acc[0][2 * ntp], a[0], b0, b1);
                mma_f16(acc[1][2 * ntp], a[1], b0, b1);
                mma_f16(acc[0][2 * ntp + 1], a[0], b2, b3);
                mma_f16(acc[1][2 * ntp + 1], a[1], b2, b3);
            }
        }

        if (more) {
            *(uint4*)((char*)&As4[buf ^ 1][0] + off0) = au[0];
            *(uint4*)((char*)&As4[buf ^ 1][0] + off1) = au[1];
            *(uint4*)((char*)&Bs4[buf ^ 1][0] + off0) = bu[0];
            *(uint4*)((char*)&Bs4[buf ^ 1][0] + off1) = bu[1];
            __syncthreads();
        }
        buf ^= 1;
    }

    // ---- fused head epilogue ----
    const int g   = lane >> 2;
    const int tig = lane & 3;
    float bvv[8][2];
#pragma unroll
    for (int nt = 0; nt < 8; nt++) {
        const int c = col0 + wn * 64 + nt * 8 + tig * 2;
        bvv[nt][0] = bias[c];
        bvv[nt][1] = bias[c + 1];
    }
    const bool addb = (col0 == 0) && (wn == 0);

#pragma unroll
    for (int mt = 0; mt < 2; mt++) {
#pragma unroll
        for (int half = 0; half < 2; half++) {
            const int r = row0 + wm * 32 + mt * 16 + g + half * 8;
            unsigned long long cls[5];
#pragma unroll
            for (int c5 = 0; c5 < 5; c5++) cls[c5] = 0ull;
#pragma unroll
            for (int nt = 0; nt < 8; nt++) {
                const int cl = wn * 64 + nt * 8 + tig * 2;
                const float v0 = gelu_f(acc[mt][nt][half * 2 + 0] + bvv[nt][0]);
                const float v1 = gelu_f(acc[mt][nt][half * 2 + 1] + bvv[nt][1]);
                const float2* w0 = (const float2*)&sWc[cl * CDIM];
                const float2* w1 = (const float2*)&sWc[(cl + 1) * CDIM];
                const unsigned long long p0 = pk_dup(v0);
                const unsigned long long p1 = pk_dup(v1);
#pragma unroll
                for (int c5 = 0; c5 < 5; c5++) {
                    const float2 a0 = w0[c5];
                    const float2 a1 = w1[c5];
                    fma2p(cls[c5], p0, pk2(a0.x, a0.y));
                    fma2p(cls[c5], p1, pk2(a1.x, a1.y));
                }
            }
            float cf[CDIM];
#pragma unroll
            for (int c5 = 0; c5 < 5; c5++) upk2(cls[c5], cf[2 * c5], cf[2 * c5 + 1]);
#pragma unroll
            for (int off = 1; off < 4; off <<= 1)
#pragma unroll
                for (int c = 0; c < CDIM; c++)
                    cf[c] += __shfl_xor_sync(0xffffffffu, cf[c], off);
            if (tig == 0 && r < Mrows) {
#pragma unroll
                for (int c = 0; c < CDIM; c++) {
                    const float add = addb ? bc2[c] : 0.f;
                    atomicAdd(&out[(long long)r * CDIM + c], cf[c] + add);
                }
            }
        }
    }
}

// ---------------------------------------------------------------------------
__global__ void prep_wh(const float* __restrict__ W, __half* __restrict__ Wt,
                        int Ksrc, int Kpad) {
    const int idx = blockIdx.x * blockDim.x + threadIdx.x;
    if (idx < DDIM * Kpad) {
        const int n = idx / Kpad, k = idx % Kpad;
        Wt[idx] = (k < Ksrc) ? __float2half((float)W[(long long)k * DDIM + n])
                             : __float2half(0.f);
    }
}

__global__ void zero_kernel(float* __restrict__ out, int G) {
    const long long total = (long long)G * DDIM;
    const long long stride = (long long)gridDim.x * blockDim.x;
    const long long i0 = (long long)blockIdx.x * blockDim.x + threadIdx.x;
    for (long long i = i0; i < total; i += stride) g_sums[i] = 0.f;
    for (long long i = i0; i < G; i += stride) g_cnt[i] = 0.f;
    for (long long i = i0; i < (long long)G * CDIM; i += stride) out[i] = 0.f;
}

// ---------------------------------------------------------------------------
extern "C" void kernel_launch(void* const* d_in, const int* in_sizes, int n_in,
                              void* d_out, int out_size)
{
    const float* h   = (const float*)d_in[0];
    const float* sf  = (const float*)d_in[1];
    const float* W1a = (const float*)d_in[2];
    const float* b1a = (const float*)d_in[3];
    const float* W2a = (const float*)d_in[4];
    const float* b2a = (const float*)d_in[5];
    const float* Wc1 = (const float*)d_in[6];
    const float* bc1 = (const float*)d_in[7];
    const float* Wc2 = (const float*)d_in[8];
    const float* bc2 = (const float*)d_in[9];
    const int* seg   = (const int*)d_in[10];
    float* out = (float*)d_out;

    const int D = in_sizes[3];
    const int N = in_sizes[0] / D;
    const int C = in_sizes[8] / D;
    const int G = out_size / C;
    const int K1 = D + in_sizes[1] / N;   // 272

    __half* wt1; cudaGetSymbolAddress((void**)&wt1, g_Wt1h);
    __half* wt2; cudaGetSymbolAddress((void**)&wt2, g_Wt2h);
    __half* wt3; cudaGetSymbolAddress((void**)&wt3, g_Wt3h);

    cudaFuncSetAttribute(fused12, cudaFuncAttributeMaxDynamicSharedMemorySize, SMEM_F);

    prep_wh<<<(D * K1PAD + 255) / 256, 256>>>(W1a, wt1, K1, K1PAD);
    prep_wh<<<(D * D + 255) / 256, 256>>>(W2a, wt2, D, D);
    prep_wh<<<(D * D + 255) / 256, 256>>>(Wc1, wt3, D, D);
    zero_kernel<<<2048, 256>>>(out, G);
    fused12<<<(N + 127) / 128, 512, SMEM_F>>>(h, sf, wt1, b1a, wt2, b2a, seg, N);
    gemm3_head<<<dim3(2, (G + 127) / 128), 256>>>(wt3, bc1, Wc2, bc2, out, G);
}